// round 1
// baseline (speedup 1.0000x reference)
#include <cuda_runtime.h>
#include <cuda_bf16.h>
#include <math.h>

// ---------------------------------------------------------------------------
// Problem constants
//   conv chain: (1,3,512,512) -> 5x [3x3 SAME conv + relu + 2x2 maxpool]
//   channels: 3->32->64->128->256->256, spatial 512->256->128->64->32->16
//   org = (256, 256) node features (channel-major)
//   graph stage on N=256 nodes, C=128 clusters, E=4096 edges
// ---------------------------------------------------------------------------

#define NNODE 256
#define NCLUS 128
#define NEDGE 4096

// Scratch (device globals; no allocation allowed)
__device__ float g_bufA[32 * 256 * 256];   // ping  (max 2.10M floats)
__device__ float g_bufB[64 * 128 * 128];   // pong  (max 1.05M floats)
__device__ float g_adj[NNODE * NNODE];
__device__ float g_agg[NNODE * NNODE];
__device__ float g_ssoft[NNODE * NCLUS];
__device__ float g_x1[NNODE * 2];
__device__ float g_tmp[NNODE * NCLUS];
__device__ float g_adjpool[NCLUS * NCLUS];
__device__ float g_nodes[NCLUS * 2];
__device__ float g_ebin[NCLUS * NCLUS];
__device__ float g_scal[2];                // [0]=link sumsq, [1]=entropy sum

// ---------------------------------------------------------------------------
// Fused conv3x3(SAME) + bias + relu + maxpool2x2 kernel.
// Each thread computes one pooled output pixel for COUT_BLK output channels.
// Block = 256 threads = 16x16 pooled tile. Input tile (34x34) + weights in smem.
// ---------------------------------------------------------------------------
#define CTH 16
#define CTW 16

template <int CIN, int COUT_BLK>
__global__ void __launch_bounds__(256)
conv_pool(const float* __restrict__ in, const float* __restrict__ w,
          const float* __restrict__ b, float* __restrict__ out,
          int H, int W) {
    constexpr int IW = 2 * CTW + 2;        // 34
    constexpr int IH = 2 * CTH + 2;        // 34
    __shared__ float s_in[IH * IW];
    __shared__ float s_w[COUT_BLK * CIN * 9];

    const int tid = threadIdx.x;
    const int tx = tid & 15, ty = tid >> 4;
    const int Ho = H >> 1, Wo = W >> 1;
    const int ox0 = blockIdx.x * CTW, oy0 = blockIdx.y * CTH;
    const int co0 = blockIdx.z * COUT_BLK;

    // cooperative weight load (contiguous: w[co][ci][3][3])
    for (int i = tid; i < COUT_BLK * CIN * 9; i += 256)
        s_w[i] = w[(size_t)co0 * CIN * 9 + i];

    float acc[COUT_BLK][4];
#pragma unroll
    for (int co = 0; co < COUT_BLK; ++co)
#pragma unroll
        for (int q = 0; q < 4; ++q) acc[co][q] = 0.f;

    const int ix0 = 2 * ox0 - 1, iy0 = 2 * oy0 - 1;

    for (int ci = 0; ci < CIN; ++ci) {
        __syncthreads();  // also guards first-use of s_w
        const float* inp = in + (size_t)ci * H * W;
        for (int i = tid; i < IH * IW; i += 256) {
            int r = i / IW, c = i - r * IW;
            int gy = iy0 + r, gx = ix0 + c;
            s_in[i] = (gy >= 0 && gy < H && gx >= 0 && gx < W)
                          ? inp[(size_t)gy * W + gx] : 0.f;
        }
        __syncthreads();

        // 4x4 input patch covering the 2x2 conv positions of this pooled pixel
        float p[16];
        const int base = (2 * ty) * IW + 2 * tx;
#pragma unroll
        for (int r = 0; r < 4; ++r)
#pragma unroll
            for (int c = 0; c < 4; ++c) p[r * 4 + c] = s_in[base + r * IW + c];

#pragma unroll
        for (int co = 0; co < COUT_BLK; ++co) {
            const float* wp = &s_w[(co * CIN + ci) * 9];
#pragma unroll
            for (int ky = 0; ky < 3; ++ky)
#pragma unroll
                for (int kx = 0; kx < 3; ++kx) {
                    float wv = wp[ky * 3 + kx];
#pragma unroll
                    for (int dy = 0; dy < 2; ++dy)
#pragma unroll
                        for (int dx = 0; dx < 2; ++dx)
                            acc[co][dy * 2 + dx] += wv * p[(dy + ky) * 4 + (dx + kx)];
                }
        }
    }

    const int oy = oy0 + ty, ox = ox0 + tx;
#pragma unroll
    for (int co = 0; co < COUT_BLK; ++co) {
        // relu(max over 2x2 of (conv+bias)) == max(relu(...)) since relu monotone
        float m = fmaxf(fmaxf(acc[co][0], acc[co][1]),
                        fmaxf(acc[co][2], acc[co][3]));
        out[(size_t)(co0 + co) * Ho * Wo + (size_t)oy * Wo + ox] =
            fmaxf(m + b[co0 + co], 0.f);
    }
}

// ---------------------------------------------------------------------------
// Graph stage kernels
// ---------------------------------------------------------------------------

__global__ void k_zero() {
    int i = blockIdx.x * blockDim.x + threadIdx.x;  // <<<256,256>>> == 65536
    g_adj[i] = 0.f;
    if (i < 2) g_scal[i] = 0.f;
}

__global__ void k_build_adj(const int* __restrict__ ei) {
    int e = blockIdx.x * blockDim.x + threadIdx.x;
    if (e < NEDGE)
        atomicAdd(&g_adj[ei[e] * NNODE + ei[NEDGE + e]], 1.f);
}

// agg[d][f] = (adj^T @ org)[d][f] / indeg(d)   (mean aggregation, guard 0)
__global__ void __launch_bounds__(256) k_agg(const float* __restrict__ org) {
    int d = blockIdx.x, f = threadIdx.x;
    float tot = 0.f, cnt = 0.f;
    for (int s = 0; s < NNODE; ++s) {
        float a = g_adj[s * NNODE + d];
        tot += a * org[s * NNODE + f];
        cnt += a;
    }
    g_agg[d * NNODE + f] = (cnt > 0.f) ? tot / cnt : 0.f;
}

// s = agg@wl2 + b2 + org@wr2; softmax per row; entropy accumulation
__global__ void __launch_bounds__(128) k_ssoft(const float* __restrict__ wl,
                                               const float* __restrict__ wr,
                                               const float* __restrict__ bb,
                                               const float* __restrict__ org) {
    int i = blockIdx.x, j = threadIdx.x;
    const float* aggr = &g_agg[i * NNODE];
    const float* orgr = org + i * NNODE;
    float v = bb[j];
    for (int k = 0; k < NNODE; ++k)
        v += aggr[k] * wl[k * NCLUS + j] + orgr[k] * wr[k * NCLUS + j];

    __shared__ float red[128];
    red[j] = v; __syncthreads();
    for (int off = 64; off > 0; off >>= 1) {
        if (j < off) red[j] = fmaxf(red[j], red[j + off]);
        __syncthreads();
    }
    float m = red[0]; __syncthreads();
    float e = expf(v - m);
    red[j] = e; __syncthreads();
    for (int off = 64; off > 0; off >>= 1) {
        if (j < off) red[j] += red[j + off];
        __syncthreads();
    }
    float p = e / red[0];
    g_ssoft[i * NCLUS + j] = p;
    float ent = -p * logf(p + 1e-15f);
    __syncthreads();
    red[j] = ent; __syncthreads();
    for (int off = 64; off > 0; off >>= 1) {
        if (j < off) red[j] += red[j + off];
        __syncthreads();
    }
    if (j == 0) atomicAdd(&g_scal[1], red[0]);
}

// x1 = agg@wl1 + b1 + org@wr1   (256 x 2)
__global__ void __launch_bounds__(256) k_x1(const float* __restrict__ wl,
                                            const float* __restrict__ wr,
                                            const float* __restrict__ bb,
                                            const float* __restrict__ org) {
    int t = blockIdx.x * 256 + threadIdx.x;  // <<<2,256>>> -> 512 threads
    int i = t >> 1, j = t & 1;
    float v = bb[j];
    const float* aggr = &g_agg[i * NNODE];
    const float* orgr = org + i * NNODE;
    for (int k = 0; k < NNODE; ++k)
        v += aggr[k] * wl[k * 2 + j] + orgr[k] * wr[k * 2 + j];
    g_x1[i * 2 + j] = v;
}

// x_pool = s_soft^T @ x1; nodes = tanh(x_pool)
__global__ void __launch_bounds__(256) k_xpool(float* __restrict__ dout) {
    int t = threadIdx.x;  // <<<1,256>>>
    int c = t >> 1, j = t & 1;
    float v = 0.f;
    for (int i = 0; i < NNODE; ++i)
        v += g_ssoft[i * NCLUS + c] * g_x1[i * 2 + j];
    float nd = tanhf(v);
    g_nodes[c * 2 + j] = nd;
    dout[258 + c * 2 + j] = nd;
}

// tmp = adj @ s_soft  (256 x 128)
__global__ void __launch_bounds__(128) k_tmp() {
    int i = blockIdx.x, c = threadIdx.x;
    const float* ar = &g_adj[i * NNODE];
    float v = 0.f;
    for (int k = 0; k < NNODE; ++k) v += ar[k] * g_ssoft[k * NCLUS + c];
    g_tmp[i * NCLUS + c] = v;
}

// adj_pool = s_soft^T @ tmp  (128 x 128)
__global__ void __launch_bounds__(128) k_adjpool() {
    int r = blockIdx.x, c = threadIdx.x;
    float v = 0.f;
    for (int i = 0; i < NNODE; ++i)
        v += g_ssoft[i * NCLUS + r] * g_tmp[i * NCLUS + c];
    g_adjpool[r * NCLUS + c] = v;
}

// link loss: sum of squares of (adj - s_soft @ s_soft^T)
__global__ void __launch_bounds__(256) k_link() {
    int i = blockIdx.x, j = threadIdx.x;
    __shared__ float rowi[128];
    if (j < 128) rowi[j] = g_ssoft[i * NCLUS + j];
    __syncthreads();
    float d = 0.f;
    const float* rj = &g_ssoft[j * NCLUS];
    for (int c = 0; c < NCLUS; ++c) d += rowi[c] * rj[c];
    float diff = g_adj[i * NNODE + j] - d;
    float sq = diff * diff;
    __shared__ float red[256];
    red[j] = sq; __syncthreads();
    for (int off = 128; off > 0; off >>= 1) {
        if (j < off) red[j] += red[j + off];
        __syncthreads();
    }
    if (j == 0) atomicAdd(&g_scal[0], red[0]);
}

// edge_bin[r][c] = (adj_pool[r][c] == rowmax(r))
__global__ void __launch_bounds__(128) k_ebin(float* __restrict__ dout) {
    int r = blockIdx.x, c = threadIdx.x;
    float v = g_adjpool[r * NCLUS + c];
    __shared__ float red[128];
    red[c] = v; __syncthreads();
    for (int off = 64; off > 0; off >>= 1) {
        if (c < off) red[c] = fmaxf(red[c], red[c + off]);
        __syncthreads();
    }
    float eb = (v == red[0]) ? 1.f : 0.f;
    g_ebin[r * NCLUS + c] = eb;
    dout[514 + r * NCLUS + c] = eb;
}

// final SAGE over binarized dense adj + scalar outputs
__global__ void __launch_bounds__(128) k_final(const float* __restrict__ wl,
                                               const float* __restrict__ wr,
                                               const float* __restrict__ bb,
                                               float* __restrict__ dout) {
    int c = threadIdx.x;  // <<<1,128>>>
    float ind = 0.f, a0 = 0.f, a1 = 0.f;
    for (int r = 0; r < NCLUS; ++r) {
        float e = g_ebin[r * NCLUS + c];
        ind += e;
        a0 += e * g_nodes[r * 2];
        a1 += e * g_nodes[r * 2 + 1];
    }
    if (ind > 0.f) { a0 /= ind; a1 /= ind; } else { a0 = 0.f; a1 = 0.f; }
    float n0 = g_nodes[c * 2], n1 = g_nodes[c * 2 + 1];
#pragma unroll
    for (int j = 0; j < 2; ++j) {
        float o = a0 * wl[j] + a1 * wl[2 + j] + bb[j] + n0 * wr[j] + n1 * wr[2 + j];
        dout[c * 2 + j] = o;
    }
    if (c == 0) {
        dout[256] = sqrtf(g_scal[0]) / 65536.f;      // norm / (N*N)
        dout[257] = g_scal[1] / 256.f;               // mean entropy
    }
}

// ---------------------------------------------------------------------------
// Launch
// ---------------------------------------------------------------------------
extern "C" void kernel_launch(void* const* d_in, const int* in_sizes, int n_in,
                              void* d_out, int out_size) {
    const float* x    = (const float*)d_in[0];
    const int*   ei   = (const int*)d_in[1];
    const float* w1   = (const float*)d_in[2];
    const float* b1   = (const float*)d_in[3];
    const float* w2   = (const float*)d_in[4];
    const float* b2   = (const float*)d_in[5];
    const float* w3   = (const float*)d_in[6];
    const float* b3   = (const float*)d_in[7];
    const float* w4   = (const float*)d_in[8];
    const float* b4   = (const float*)d_in[9];
    const float* w5   = (const float*)d_in[10];
    const float* b5   = (const float*)d_in[11];
    const float* s1wl = (const float*)d_in[12];
    const float* s1wr = (const float*)d_in[13];
    const float* s1b  = (const float*)d_in[14];
    const float* s2wl = (const float*)d_in[15];
    const float* s2wr = (const float*)d_in[16];
    const float* s2b  = (const float*)d_in[17];
    const float* s3wl = (const float*)d_in[18];
    const float* s3wr = (const float*)d_in[19];
    const float* s3b  = (const float*)d_in[20];
    float* dout = (float*)d_out;

    float *bufA, *bufB;
    cudaGetSymbolAddress((void**)&bufA, g_bufA);
    cudaGetSymbolAddress((void**)&bufB, g_bufB);

    // conv chain (fused conv+relu+pool, fp32 direct)
    conv_pool<3, 4><<<dim3(16, 16, 8),  256>>>(x,    w1, b1, bufA, 512, 512);
    conv_pool<32, 4><<<dim3(8, 8, 16),  256>>>(bufA, w2, b2, bufB, 256, 256);
    conv_pool<64, 4><<<dim3(4, 4, 32),  256>>>(bufB, w3, b3, bufA, 128, 128);
    conv_pool<128, 4><<<dim3(2, 2, 64), 256>>>(bufA, w4, b4, bufB, 64, 64);
    conv_pool<256, 2><<<dim3(1, 1, 128), 256>>>(bufB, w5, b5, bufA, 32, 32);
    // org = bufA (256 x 256)

    // graph stage
    k_zero<<<256, 256>>>();
    k_build_adj<<<16, 256>>>(ei);
    k_agg<<<256, 256>>>(bufA);
    k_ssoft<<<256, 128>>>(s2wl, s2wr, s2b, bufA);
    k_x1<<<2, 256>>>(s1wl, s1wr, s1b, bufA);
    k_xpool<<<1, 256>>>(dout);
    k_tmp<<<256, 128>>>();
    k_adjpool<<<128, 128>>>();
    k_link<<<256, 256>>>();
    k_ebin<<<128, 128>>>(dout);
    k_final<<<1, 128>>>(s3wl, s3wr, s3b, dout);
}

// round 2
// speedup vs baseline: 2.2684x; 2.2684x over previous
#include <cuda_runtime.h>
#include <cuda_bf16.h>
#include <math.h>

// ---------------------------------------------------------------------------
// Problem constants
// ---------------------------------------------------------------------------
#define NNODE 256
#define NCLUS 128
#define NEDGE 4096

// Scratch (device globals; no allocation allowed)
__device__ __align__(16) float g_bufA[32 * 256 * 256];   // 2.10M floats
__device__ __align__(16) float g_bufB[64 * 128 * 128];   // 1.05M floats
__device__ __align__(16) float g_part[4 * 256 * 32 * 32 * 4]; // split-K partials (4.19M floats)
__device__ float g_adj[NNODE * NNODE];
__device__ float g_agg[NNODE * NNODE];
__device__ float g_ssoft[NNODE * NCLUS];
__device__ float g_x1[NNODE * 2];
__device__ float g_tmp[NNODE * NCLUS];
__device__ float g_adjpool[NCLUS * NCLUS];
__device__ float g_nodes[NCLUS * 2];
__device__ float g_ebin[NCLUS * NCLUS];
__device__ float g_scal[2];

// ---------------------------------------------------------------------------
// Fused conv3x3(SAME)+bias+relu+maxpool2x2, double-buffered smem tiles.
// Block = 256 threads = 16x16 pooled tile, COUT_BLK output channels/thread.
// SPLIT=true: computes a Cin chunk, writes pre-pool partial quads (float4).
// ---------------------------------------------------------------------------
template <int CIN_TOT, int CHUNK, int COUT_BLK, bool SPLIT>
__global__ void __launch_bounds__(256, 2)
conv_k(const float* __restrict__ in, const float* __restrict__ w,
       const float* __restrict__ bias, float* __restrict__ out,
       int H, int W, int ncog, int Cout) {
    constexpr int IW = 34, IH = 34;
    constexpr int TILE = IH * IW;                  // 1156
    __shared__ float s_in[2][TILE];
    __shared__ float s_w[COUT_BLK * CHUNK * 9];

    const int tid = threadIdx.x;
    const int tx = tid & 15, ty = tid >> 4;
    const int Ho = H >> 1, Wo = W >> 1;

    int zc = blockIdx.z;
    const int chunk = SPLIT ? zc / ncog : 0;
    const int cog   = SPLIT ? zc % ncog : zc;
    const int co0 = cog * COUT_BLK;
    const int ci0 = chunk * CHUNK;

    const int ox0 = blockIdx.x * 16, oy0 = blockIdx.y * 16;
    const int ix0 = 2 * ox0 - 1, iy0 = 2 * oy0 - 1;
    const bool interior = (ix0 >= 0) && (iy0 >= 0) &&
                          (ix0 + IW <= W) && (iy0 + IH <= H);

    // weights for [co0, co0+COUT_BLK) x [ci0, ci0+CHUNK): contiguous per co
    for (int i = tid; i < COUT_BLK * CHUNK * 9; i += 256) {
        int co = i / (CHUNK * 9);
        int rem = i - co * (CHUNK * 9);
        s_w[i] = w[((size_t)(co0 + co) * CIN_TOT + ci0) * 9 + rem];
    }

    float acc[COUT_BLK][4];
#pragma unroll
    for (int co = 0; co < COUT_BLK; ++co)
#pragma unroll
        for (int q = 0; q < 4; ++q) acc[co][q] = 0.f;

    auto load_tile = [&](int ci, float* dst) {
        const float* inp = in + (size_t)(ci0 + ci) * H * W;
        if (interior) {
#pragma unroll
            for (int k = 0; k < 5; ++k) {
                int i = tid + k * 256;
                if (i < TILE) {
                    int r = i / IW, c = i - r * IW;
                    dst[i] = inp[(size_t)(iy0 + r) * W + ix0 + c];
                }
            }
        } else {
#pragma unroll
            for (int k = 0; k < 5; ++k) {
                int i = tid + k * 256;
                if (i < TILE) {
                    int r = i / IW, c = i - r * IW;
                    int gy = iy0 + r, gx = ix0 + c;
                    dst[i] = (gy >= 0 && gy < H && gx >= 0 && gx < W)
                                 ? inp[(size_t)gy * W + gx] : 0.f;
                }
            }
        }
    };

    load_tile(0, s_in[0]);
    __syncthreads();   // also guards s_w

    const int base = (2 * ty) * IW + 2 * tx;
    for (int ci = 0; ci < CHUNK; ++ci) {
        const int cur = ci & 1;
        if (ci + 1 < CHUNK) load_tile(ci + 1, s_in[cur ^ 1]);

        float p[16];
        const float* sp = s_in[cur] + base;
#pragma unroll
        for (int r = 0; r < 4; ++r)
#pragma unroll
            for (int c = 0; c < 4; ++c) p[r * 4 + c] = sp[r * IW + c];

#pragma unroll
        for (int co = 0; co < COUT_BLK; ++co) {
            float wv[9];
            const float* wp = &s_w[(co * CHUNK + ci) * 9];
#pragma unroll
            for (int t = 0; t < 9; ++t) wv[t] = wp[t];
#pragma unroll
            for (int ky = 0; ky < 3; ++ky)
#pragma unroll
                for (int kx = 0; kx < 3; ++kx) {
                    float wvv = wv[ky * 3 + kx];
#pragma unroll
                    for (int dy = 0; dy < 2; ++dy)
#pragma unroll
                        for (int dx = 0; dx < 2; ++dx)
                            acc[co][dy * 2 + dx] += wvv * p[(dy + ky) * 4 + (dx + kx)];
                }
        }
        __syncthreads();
    }

    if (!SPLIT) {
        const int oy = oy0 + ty, ox = ox0 + tx;
#pragma unroll
        for (int co = 0; co < COUT_BLK; ++co) {
            float m = fmaxf(fmaxf(acc[co][0], acc[co][1]),
                            fmaxf(acc[co][2], acc[co][3]));
            out[(size_t)(co0 + co) * Ho * Wo + (size_t)oy * Wo + ox] =
                fmaxf(m + bias[co0 + co], 0.f);
        }
    } else {
        const int y = oy0 + ty, x = ox0 + tx;
        float4* o4 = (float4*)out;
#pragma unroll
        for (int co = 0; co < COUT_BLK; ++co) {
            float4 v = make_float4(acc[co][0], acc[co][1], acc[co][2], acc[co][3]);
            o4[((size_t)(chunk * Cout + co0 + co) * Ho + y) * Wo + x] = v;
        }
    }
}

// sum split-K partial quads + bias + relu + 2x2 max
__global__ void __launch_bounds__(256)
reduce_pool(const float4* __restrict__ part, const float* __restrict__ bias,
            float* __restrict__ out, int Cout, int Ho, int Wo, int nchunk) {
    int idx = blockIdx.x * 256 + threadIdx.x;
    int total = Cout * Ho * Wo;
    if (idx >= total) return;
    int stride = total;
    float4 s = make_float4(0.f, 0.f, 0.f, 0.f);
    for (int k = 0; k < nchunk; ++k) {
        float4 v = part[(size_t)k * stride + idx];
        s.x += v.x; s.y += v.y; s.z += v.z; s.w += v.w;
    }
    int co = idx / (Ho * Wo);
    float m = fmaxf(fmaxf(s.x, s.y), fmaxf(s.z, s.w));
    out[idx] = fmaxf(m + bias[co], 0.f);
}

// ---------------------------------------------------------------------------
// Graph stage kernels (unchanged from R1, verified correct)
// ---------------------------------------------------------------------------
__global__ void k_zero() {
    int i = blockIdx.x * blockDim.x + threadIdx.x;
    g_adj[i] = 0.f;
    if (i < 2) g_scal[i] = 0.f;
}

__global__ void k_build_adj(const int* __restrict__ ei) {
    int e = blockIdx.x * blockDim.x + threadIdx.x;
    if (e < NEDGE)
        atomicAdd(&g_adj[ei[e] * NNODE + ei[NEDGE + e]], 1.f);
}

__global__ void __launch_bounds__(256) k_agg(const float* __restrict__ org) {
    int d = blockIdx.x, f = threadIdx.x;
    float tot = 0.f, cnt = 0.f;
    for (int s = 0; s < NNODE; ++s) {
        float a = g_adj[s * NNODE + d];
        tot += a * org[s * NNODE + f];
        cnt += a;
    }
    g_agg[d * NNODE + f] = (cnt > 0.f) ? tot / cnt : 0.f;
}

__global__ void __launch_bounds__(128) k_ssoft(const float* __restrict__ wl,
                                               const float* __restrict__ wr,
                                               const float* __restrict__ bb,
                                               const float* __restrict__ org) {
    int i = blockIdx.x, j = threadIdx.x;
    const float* aggr = &g_agg[i * NNODE];
    const float* orgr = org + i * NNODE;
    float v = bb[j];
    for (int k = 0; k < NNODE; ++k)
        v += aggr[k] * wl[k * NCLUS + j] + orgr[k] * wr[k * NCLUS + j];

    __shared__ float red[128];
    red[j] = v; __syncthreads();
    for (int off = 64; off > 0; off >>= 1) {
        if (j < off) red[j] = fmaxf(red[j], red[j + off]);
        __syncthreads();
    }
    float m = red[0]; __syncthreads();
    float e = expf(v - m);
    red[j] = e; __syncthreads();
    for (int off = 64; off > 0; off >>= 1) {
        if (j < off) red[j] += red[j + off];
        __syncthreads();
    }
    float p = e / red[0];
    g_ssoft[i * NCLUS + j] = p;
    float ent = -p * logf(p + 1e-15f);
    __syncthreads();
    red[j] = ent; __syncthreads();
    for (int off = 64; off > 0; off >>= 1) {
        if (j < off) red[j] += red[j + off];
        __syncthreads();
    }
    if (j == 0) atomicAdd(&g_scal[1], red[0]);
}

__global__ void __launch_bounds__(256) k_x1(const float* __restrict__ wl,
                                            const float* __restrict__ wr,
                                            const float* __restrict__ bb,
                                            const float* __restrict__ org) {
    int t = blockIdx.x * 256 + threadIdx.x;
    int i = t >> 1, j = t & 1;
    float v = bb[j];
    const float* aggr = &g_agg[i * NNODE];
    const float* orgr = org + i * NNODE;
    for (int k = 0; k < NNODE; ++k)
        v += aggr[k] * wl[k * 2 + j] + orgr[k] * wr[k * 2 + j];
    g_x1[i * 2 + j] = v;
}

__global__ void __launch_bounds__(256) k_xpool(float* __restrict__ dout) {
    int t = threadIdx.x;
    int c = t >> 1, j = t & 1;
    float v = 0.f;
    for (int i = 0; i < NNODE; ++i)
        v += g_ssoft[i * NCLUS + c] * g_x1[i * 2 + j];
    float nd = tanhf(v);
    g_nodes[c * 2 + j] = nd;
    dout[258 + c * 2 + j] = nd;
}

__global__ void __launch_bounds__(128) k_tmp() {
    int i = blockIdx.x, c = threadIdx.x;
    const float* ar = &g_adj[i * NNODE];
    float v = 0.f;
    for (int k = 0; k < NNODE; ++k) v += ar[k] * g_ssoft[k * NCLUS + c];
    g_tmp[i * NCLUS + c] = v;
}

__global__ void __launch_bounds__(128) k_adjpool() {
    int r = blockIdx.x, c = threadIdx.x;
    float v = 0.f;
    for (int i = 0; i < NNODE; ++i)
        v += g_ssoft[i * NCLUS + r] * g_tmp[i * NCLUS + c];
    g_adjpool[r * NCLUS + c] = v;
}

__global__ void __launch_bounds__(256) k_link() {
    int i = blockIdx.x, j = threadIdx.x;
    __shared__ float rowi[128];
    if (j < 128) rowi[j] = g_ssoft[i * NCLUS + j];
    __syncthreads();
    float d = 0.f;
    const float* rj = &g_ssoft[j * NCLUS];
    for (int c = 0; c < NCLUS; ++c) d += rowi[c] * rj[c];
    float diff = g_adj[i * NNODE + j] - d;
    float sq = diff * diff;
    __shared__ float red[256];
    red[j] = sq; __syncthreads();
    for (int off = 128; off > 0; off >>= 1) {
        if (j < off) red[j] += red[j + off];
        __syncthreads();
    }
    if (j == 0) atomicAdd(&g_scal[0], red[0]);
}

__global__ void __launch_bounds__(128) k_ebin(float* __restrict__ dout) {
    int r = blockIdx.x, c = threadIdx.x;
    float v = g_adjpool[r * NCLUS + c];
    __shared__ float red[128];
    red[c] = v; __syncthreads();
    for (int off = 64; off > 0; off >>= 1) {
        if (c < off) red[c] = fmaxf(red[c], red[c + off]);
        __syncthreads();
    }
    float eb = (v == red[0]) ? 1.f : 0.f;
    g_ebin[r * NCLUS + c] = eb;
    dout[514 + r * NCLUS + c] = eb;
}

__global__ void __launch_bounds__(128) k_final(const float* __restrict__ wl,
                                               const float* __restrict__ wr,
                                               const float* __restrict__ bb,
                                               float* __restrict__ dout) {
    int c = threadIdx.x;
    float ind = 0.f, a0 = 0.f, a1 = 0.f;
    for (int r = 0; r < NCLUS; ++r) {
        float e = g_ebin[r * NCLUS + c];
        ind += e;
        a0 += e * g_nodes[r * 2];
        a1 += e * g_nodes[r * 2 + 1];
    }
    if (ind > 0.f) { a0 /= ind; a1 /= ind; } else { a0 = 0.f; a1 = 0.f; }
    float n0 = g_nodes[c * 2], n1 = g_nodes[c * 2 + 1];
#pragma unroll
    for (int j = 0; j < 2; ++j) {
        float o = a0 * wl[j] + a1 * wl[2 + j] + bb[j] + n0 * wr[j] + n1 * wr[2 + j];
        dout[c * 2 + j] = o;
    }
    if (c == 0) {
        dout[256] = sqrtf(g_scal[0]) / 65536.f;
        dout[257] = g_scal[1] / 256.f;
    }
}

// ---------------------------------------------------------------------------
// Launch
// ---------------------------------------------------------------------------
extern "C" void kernel_launch(void* const* d_in, const int* in_sizes, int n_in,
                              void* d_out, int out_size) {
    const float* x    = (const float*)d_in[0];
    const int*   ei   = (const int*)d_in[1];
    const float* w1   = (const float*)d_in[2];
    const float* b1   = (const float*)d_in[3];
    const float* w2   = (const float*)d_in[4];
    const float* b2   = (const float*)d_in[5];
    const float* w3   = (const float*)d_in[6];
    const float* b3   = (const float*)d_in[7];
    const float* w4   = (const float*)d_in[8];
    const float* b4   = (const float*)d_in[9];
    const float* w5   = (const float*)d_in[10];
    const float* b5   = (const float*)d_in[11];
    const float* s1wl = (const float*)d_in[12];
    const float* s1wr = (const float*)d_in[13];
    const float* s1b  = (const float*)d_in[14];
    const float* s2wl = (const float*)d_in[15];
    const float* s2wr = (const float*)d_in[16];
    const float* s2b  = (const float*)d_in[17];
    const float* s3wl = (const float*)d_in[18];
    const float* s3wr = (const float*)d_in[19];
    const float* s3b  = (const float*)d_in[20];
    float* dout = (float*)d_out;

    float *bufA, *bufB, *part;
    cudaGetSymbolAddress((void**)&bufA, g_bufA);
    cudaGetSymbolAddress((void**)&bufB, g_bufB);
    cudaGetSymbolAddress((void**)&part, g_part);

    // conv chain
    conv_k<3, 3, 8, false><<<dim3(16, 16, 4), 256>>>(x,    w1, b1, bufA, 512, 512, 0, 32);
    conv_k<32, 32, 8, false><<<dim3(8, 8, 8), 256>>>(bufA, w2, b2, bufB, 256, 256, 0, 64);
    conv_k<64, 64, 8, false><<<dim3(4, 4, 16), 256>>>(bufB, w3, b3, bufA, 128, 128, 0, 128);
    // L4 split-K: 4 chunks x 32 co-groups
    conv_k<128, 32, 8, true><<<dim3(2, 2, 128), 256>>>(bufA, w4, b4, part, 64, 64, 32, 256);
    reduce_pool<<<1024, 256>>>((const float4*)part, b4, bufB, 256, 32, 32, 4);
    // L5 split-K: 8 chunks x 32 co-groups
    conv_k<256, 32, 8, true><<<dim3(1, 1, 256), 256>>>(bufB, w5, b5, part, 32, 32, 32, 256);
    reduce_pool<<<256, 256>>>((const float4*)part, b5, bufA, 256, 16, 16, 8);
    // org = bufA (256 x 256)

    // graph stage
    k_zero<<<256, 256>>>();
    k_build_adj<<<16, 256>>>(ei);
    k_agg<<<256, 256>>>(bufA);
    k_ssoft<<<256, 128>>>(s2wl, s2wr, s2b, bufA);
    k_x1<<<2, 256>>>(s1wl, s1wr, s1b, bufA);
    k_xpool<<<1, 256>>>(dout);
    k_tmp<<<256, 128>>>();
    k_adjpool<<<128, 128>>>();
    k_link<<<256, 256>>>();
    k_ebin<<<128, 128>>>(dout);
    k_final<<<1, 128>>>(s3wl, s3wr, s3b, dout);
}

// round 3
// speedup vs baseline: 2.5417x; 1.1205x over previous
#include <cuda_runtime.h>
#include <cuda_bf16.h>
#include <math.h>

// ---------------------------------------------------------------------------
#define NNODE 256
#define NCLUS 128
#define NEDGE 4096

// Scratch (device globals)
__device__ __align__(16) float g_bufA[32 * 258 * 258];        // 2.13M floats
__device__ __align__(16) float g_bufB[64 * 130 * 130];        // 1.08M floats
__device__ __align__(16) float g_part[4 * 256 * 32 * 32 * 4]; // 4.19M floats
__device__ float g_adj[NNODE * NNODE];
__device__ float g_agg[NNODE * NNODE];
__device__ float g_ssoft[NNODE * NCLUS];
__device__ float g_x1[NNODE * 2];
__device__ float g_tmp[NNODE * NCLUS];
__device__ float g_adjpool[NCLUS * NCLUS];
__device__ float g_nodes[NCLUS * 2];
__device__ float g_ebin[NCLUS * NCLUS];
__device__ float g_scal[2];

__global__ void k_clear(float* __restrict__ p, int n) {
    for (int i = blockIdx.x * blockDim.x + threadIdx.x; i < n;
         i += gridDim.x * blockDim.x)
        p[i] = 0.f;
}

// ---------------------------------------------------------------------------
// Fused conv3x3(SAME)+bias+relu+maxpool2x2.
// Block = 256 threads = 16x16 pooled tile, COUT_BLK output channels/thread.
// PADIN/PADOUT: gmem tensors have a 1-pixel zero border (stride W+2).
// SPLIT: computes a Cin chunk, writes pre-pool partial quads (float4).
// ---------------------------------------------------------------------------
template <int CIN_TOT, int CHUNK, int COUT_BLK, bool SPLIT, bool PADIN, bool PADOUT>
__global__ void __launch_bounds__(256, 2)
conv_k(const float* __restrict__ in, const float* __restrict__ w,
       const float* __restrict__ bias, float* __restrict__ out,
       int H, int W, int ncog, int Cout) {
    constexpr int IW = 34, IH = 34;
    constexpr int TILE = IH * IW;                  // 1156
    __shared__ __align__(16) float s_in[2][TILE];
    __shared__ __align__(16) float s_w[CHUNK * COUT_BLK * 12];

    const int tid = threadIdx.x;
    const int tx = tid & 15, ty = tid >> 4;
    const int Ho = H >> 1, Wo = W >> 1;

    const int zc = blockIdx.z;
    const int chunk = SPLIT ? zc / ncog : 0;
    const int cog   = SPLIT ? zc % ncog : zc;
    const int co0 = cog * COUT_BLK;
    const int ci0 = chunk * CHUNK;

    const int ox0 = blockIdx.x * 16, oy0 = blockIdx.y * 16;
    const int ix0 = 2 * ox0 - 1, iy0 = 2 * oy0 - 1;
    const bool interior = PADIN || ((ix0 >= 0) && (iy0 >= 0) &&
                                    (ix0 + IW <= W) && (iy0 + IH <= H));

    // weights: gmem [co][ci][9] -> smem [ci][co][12] (16B records for LDS.128)
    for (int i = tid; i < COUT_BLK * CHUNK * 9; i += 256) {
        int co = i / (CHUNK * 9);
        int rem = i - co * (CHUNK * 9);
        int ci = rem / 9;
        int t = rem - ci * 9;
        s_w[(ci * COUT_BLK + co) * 12 + t] =
            w[((size_t)(co0 + co) * CIN_TOT + ci0) * 9 + rem];
    }

    float acc[COUT_BLK][4];
#pragma unroll
    for (int co = 0; co < COUT_BLK; ++co)
#pragma unroll
        for (int q = 0; q < 4; ++q) acc[co][q] = 0.f;

    const int Wp = PADIN ? W + 2 : W;
    const int plane = PADIN ? (H + 2) * (W + 2) : H * W;

    auto load_tile = [&](int ci, float* dst) {
        const float* inp = in + (size_t)(ci0 + ci) * plane;
        if (PADIN) {
            // padded: unconditional loads; (iy0+1)=2*oy0, (ix0+1)=2*ox0
#pragma unroll
            for (int k = 0; k < 5; ++k) {
                int i = tid + k * 256;
                if (i < TILE) {
                    int r = i / IW, c = i - r * IW;
                    dst[i] = inp[(size_t)(2 * oy0 + r) * Wp + 2 * ox0 + c];
                }
            }
        } else if (interior) {
#pragma unroll
            for (int k = 0; k < 5; ++k) {
                int i = tid + k * 256;
                if (i < TILE) {
                    int r = i / IW, c = i - r * IW;
                    dst[i] = inp[(size_t)(iy0 + r) * W + ix0 + c];
                }
            }
        } else {
#pragma unroll
            for (int k = 0; k < 5; ++k) {
                int i = tid + k * 256;
                if (i < TILE) {
                    int r = i / IW, c = i - r * IW;
                    int gy = iy0 + r, gx = ix0 + c;
                    dst[i] = (gy >= 0 && gy < H && gx >= 0 && gx < W)
                                 ? inp[(size_t)gy * W + gx] : 0.f;
                }
            }
        }
    };

    load_tile(0, s_in[0]);
    __syncthreads();   // also guards s_w

    const int base = (2 * ty) * IW + 2 * tx;   // even -> 8B aligned
    for (int ci = 0; ci < CHUNK; ++ci) {
        const int cur = ci & 1;
        if (ci + 1 < CHUNK) load_tile(ci + 1, s_in[cur ^ 1]);

        // 4x4 input patch as 8 x LDS.64
        float p[16];
        const float* sp = s_in[cur] + base;
#pragma unroll
        for (int r = 0; r < 4; ++r) {
            float2 a = *(const float2*)(sp + r * IW);
            float2 b = *(const float2*)(sp + r * IW + 2);
            p[r * 4 + 0] = a.x; p[r * 4 + 1] = a.y;
            p[r * 4 + 2] = b.x; p[r * 4 + 3] = b.y;
        }

#pragma unroll
        for (int co = 0; co < COUT_BLK; ++co) {
            const float4* wq = (const float4*)(s_w + (ci * COUT_BLK + co) * 12);
            float4 wa = wq[0], wb = wq[1], wc = wq[2];
            float wv[9] = {wa.x, wa.y, wa.z, wa.w, wb.x, wb.y, wb.z, wb.w, wc.x};
#pragma unroll
            for (int ky = 0; ky < 3; ++ky)
#pragma unroll
                for (int kx = 0; kx < 3; ++kx) {
                    float wvv = wv[ky * 3 + kx];
#pragma unroll
                    for (int dy = 0; dy < 2; ++dy)
#pragma unroll
                        for (int dx = 0; dx < 2; ++dx)
                            acc[co][dy * 2 + dx] += wvv * p[(dy + ky) * 4 + (dx + kx)];
                }
        }
        __syncthreads();
    }

    if (!SPLIT) {
        const int oy = oy0 + ty, ox = ox0 + tx;
#pragma unroll
        for (int co = 0; co < COUT_BLK; ++co) {
            float m = fmaxf(fmaxf(acc[co][0], acc[co][1]),
                            fmaxf(acc[co][2], acc[co][3]));
            float v = fmaxf(m + bias[co0 + co], 0.f);
            if (PADOUT)
                out[((size_t)(co0 + co) * (Ho + 2) + oy + 1) * (Wo + 2) + ox + 1] = v;
            else
                out[(size_t)(co0 + co) * Ho * Wo + (size_t)oy * Wo + ox] = v;
        }
    } else {
        const int y = oy0 + ty, x = ox0 + tx;
        float4* o4 = (float4*)out;
#pragma unroll
        for (int co = 0; co < COUT_BLK; ++co) {
            float4 v = make_float4(acc[co][0], acc[co][1], acc[co][2], acc[co][3]);
            o4[((size_t)(chunk * Cout + co0 + co) * Ho + y) * Wo + x] = v;
        }
    }
}

// sum split-K partial quads + bias + relu + 2x2 max
template <bool PADOUT>
__global__ void __launch_bounds__(256)
reduce_pool(const float4* __restrict__ part, const float* __restrict__ bias,
            float* __restrict__ out, int Cout, int Ho, int Wo, int nchunk) {
    int idx = blockIdx.x * 256 + threadIdx.x;
    int total = Cout * Ho * Wo;
    if (idx >= total) return;
    float4 s = make_float4(0.f, 0.f, 0.f, 0.f);
    for (int k = 0; k < nchunk; ++k) {
        float4 v = part[(size_t)k * total + idx];
        s.x += v.x; s.y += v.y; s.z += v.z; s.w += v.w;
    }
    int co = idx / (Ho * Wo);
    int rem = idx - co * Ho * Wo;
    int y = rem / Wo, x = rem - y * Wo;
    float m = fmaxf(fmaxf(s.x, s.y), fmaxf(s.z, s.w));
    float v = fmaxf(m + bias[co], 0.f);
    if (PADOUT)
        out[((size_t)co * (Ho + 2) + y + 1) * (Wo + 2) + x + 1] = v;
    else
        out[idx] = v;
}

// ---------------------------------------------------------------------------
// Graph stage kernels (verified correct in R1/R2)
// ---------------------------------------------------------------------------
__global__ void k_zero() {
    int i = blockIdx.x * blockDim.x + threadIdx.x;
    g_adj[i] = 0.f;
    if (i < 2) g_scal[i] = 0.f;
}

__global__ void k_build_adj(const int* __restrict__ ei) {
    int e = blockIdx.x * blockDim.x + threadIdx.x;
    if (e < NEDGE)
        atomicAdd(&g_adj[ei[e] * NNODE + ei[NEDGE + e]], 1.f);
}

__global__ void __launch_bounds__(256) k_agg(const float* __restrict__ org) {
    int d = blockIdx.x, f = threadIdx.x;
    float tot = 0.f, cnt = 0.f;
    for (int s = 0; s < NNODE; ++s) {
        float a = g_adj[s * NNODE + d];
        tot += a * org[s * NNODE + f];
        cnt += a;
    }
    g_agg[d * NNODE + f] = (cnt > 0.f) ? tot / cnt : 0.f;
}

__global__ void __launch_bounds__(128) k_ssoft(const float* __restrict__ wl,
                                               const float* __restrict__ wr,
                                               const float* __restrict__ bb,
                                               const float* __restrict__ org) {
    int i = blockIdx.x, j = threadIdx.x;
    const float* aggr = &g_agg[i * NNODE];
    const float* orgr = org + i * NNODE;
    float v = bb[j];
    for (int k = 0; k < NNODE; ++k)
        v += aggr[k] * wl[k * NCLUS + j] + orgr[k] * wr[k * NCLUS + j];

    __shared__ float red[128];
    red[j] = v; __syncthreads();
    for (int off = 64; off > 0; off >>= 1) {
        if (j < off) red[j] = fmaxf(red[j], red[j + off]);
        __syncthreads();
    }
    float m = red[0]; __syncthreads();
    float e = expf(v - m);
    red[j] = e; __syncthreads();
    for (int off = 64; off > 0; off >>= 1) {
        if (j < off) red[j] += red[j + off];
        __syncthreads();
    }
    float p = e / red[0];
    g_ssoft[i * NCLUS + j] = p;
    float ent = -p * logf(p + 1e-15f);
    __syncthreads();
    red[j] = ent; __syncthreads();
    for (int off = 64; off > 0; off >>= 1) {
        if (j < off) red[j] += red[j + off];
        __syncthreads();
    }
    if (j == 0) atomicAdd(&g_scal[1], red[0]);
}

__global__ void __launch_bounds__(256) k_x1(const float* __restrict__ wl,
                                            const float* __restrict__ wr,
                                            const float* __restrict__ bb,
                                            const float* __restrict__ org) {
    int t = blockIdx.x * 256 + threadIdx.x;
    int i = t >> 1, j = t & 1;
    float v = bb[j];
    const float* aggr = &g_agg[i * NNODE];
    const float* orgr = org + i * NNODE;
    for (int k = 0; k < NNODE; ++k)
        v += aggr[k] * wl[k * 2 + j] + orgr[k] * wr[k * 2 + j];
    g_x1[i * 2 + j] = v;
}

__global__ void __launch_bounds__(256) k_xpool(float* __restrict__ dout) {
    int t = threadIdx.x;
    int c = t >> 1, j = t & 1;
    float v = 0.f;
    for (int i = 0; i < NNODE; ++i)
        v += g_ssoft[i * NCLUS + c] * g_x1[i * 2 + j];
    float nd = tanhf(v);
    g_nodes[c * 2 + j] = nd;
    dout[258 + c * 2 + j] = nd;
}

__global__ void __launch_bounds__(128) k_tmp() {
    int i = blockIdx.x, c = threadIdx.x;
    const float* ar = &g_adj[i * NNODE];
    float v = 0.f;
    for (int k = 0; k < NNODE; ++k) v += ar[k] * g_ssoft[k * NCLUS + c];
    g_tmp[i * NCLUS + c] = v;
}

__global__ void __launch_bounds__(128) k_adjpool() {
    int r = blockIdx.x, c = threadIdx.x;
    float v = 0.f;
    for (int i = 0; i < NNODE; ++i)
        v += g_ssoft[i * NCLUS + r] * g_tmp[i * NCLUS + c];
    g_adjpool[r * NCLUS + c] = v;
}

__global__ void __launch_bounds__(256) k_link() {
    int i = blockIdx.x, j = threadIdx.x;
    __shared__ float rowi[128];
    if (j < 128) rowi[j] = g_ssoft[i * NCLUS + j];
    __syncthreads();
    float d = 0.f;
    const float* rj = &g_ssoft[j * NCLUS];
    for (int c = 0; c < NCLUS; ++c) d += rowi[c] * rj[c];
    float diff = g_adj[i * NNODE + j] - d;
    float sq = diff * diff;
    __shared__ float red[256];
    red[j] = sq; __syncthreads();
    for (int off = 128; off > 0; off >>= 1) {
        if (j < off) red[j] += red[j + off];
        __syncthreads();
    }
    if (j == 0) atomicAdd(&g_scal[0], red[0]);
}

__global__ void __launch_bounds__(128) k_ebin(float* __restrict__ dout) {
    int r = blockIdx.x, c = threadIdx.x;
    float v = g_adjpool[r * NCLUS + c];
    __shared__ float red[128];
    red[c] = v; __syncthreads();
    for (int off = 64; off > 0; off >>= 1) {
        if (c < off) red[c] = fmaxf(red[c], red[c + off]);
        __syncthreads();
    }
    float eb = (v == red[0]) ? 1.f : 0.f;
    g_ebin[r * NCLUS + c] = eb;
    dout[514 + r * NCLUS + c] = eb;
}

__global__ void __launch_bounds__(128) k_final(const float* __restrict__ wl,
                                               const float* __restrict__ wr,
                                               const float* __restrict__ bb,
                                               float* __restrict__ dout) {
    int c = threadIdx.x;
    float ind = 0.f, a0 = 0.f, a1 = 0.f;
    for (int r = 0; r < NCLUS; ++r) {
        float e = g_ebin[r * NCLUS + c];
        ind += e;
        a0 += e * g_nodes[r * 2];
        a1 += e * g_nodes[r * 2 + 1];
    }
    if (ind > 0.f) { a0 /= ind; a1 /= ind; } else { a0 = 0.f; a1 = 0.f; }
    float n0 = g_nodes[c * 2], n1 = g_nodes[c * 2 + 1];
#pragma unroll
    for (int j = 0; j < 2; ++j) {
        float o = a0 * wl[j] + a1 * wl[2 + j] + bb[j] + n0 * wr[j] + n1 * wr[2 + j];
        dout[c * 2 + j] = o;
    }
    if (c == 0) {
        dout[256] = sqrtf(g_scal[0]) / 65536.f;
        dout[257] = g_scal[1] / 256.f;
    }
}

// ---------------------------------------------------------------------------
extern "C" void kernel_launch(void* const* d_in, const int* in_sizes, int n_in,
                              void* d_out, int out_size) {
    const float* x    = (const float*)d_in[0];
    const int*   ei   = (const int*)d_in[1];
    const float* w1   = (const float*)d_in[2];
    const float* b1   = (const float*)d_in[3];
    const float* w2   = (const float*)d_in[4];
    const float* b2   = (const float*)d_in[5];
    const float* w3   = (const float*)d_in[6];
    const float* b3   = (const float*)d_in[7];
    const float* w4   = (const float*)d_in[8];
    const float* b4   = (const float*)d_in[9];
    const float* w5   = (const float*)d_in[10];
    const float* b5   = (const float*)d_in[11];
    const float* s1wl = (const float*)d_in[12];
    const float* s1wr = (const float*)d_in[13];
    const float* s1b  = (const float*)d_in[14];
    const float* s2wl = (const float*)d_in[15];
    const float* s2wr = (const float*)d_in[16];
    const float* s2b  = (const float*)d_in[17];
    const float* s3wl = (const float*)d_in[18];
    const float* s3wr = (const float*)d_in[19];
    const float* s3b  = (const float*)d_in[20];
    float* dout = (float*)d_out;

    float *bufA, *bufB, *part;
    cudaGetSymbolAddress((void**)&bufA, g_bufA);
    cudaGetSymbolAddress((void**)&bufB, g_bufB);
    cudaGetSymbolAddress((void**)&part, g_part);

    // L1: 3->32, 512x512 -> padded out (258x258)
    k_clear<<<2048, 256>>>(bufA, 32 * 258 * 258);
    conv_k<3, 3, 16, false, false, true><<<dim3(16, 16, 2), 256>>>(
        x, w1, b1, bufA, 512, 512, 0, 32);
    // L2: 32->64, 256x256 -> padded out (130x130)
    k_clear<<<1024, 256>>>(bufB, 64 * 130 * 130);
    conv_k<32, 32, 16, false, true, true><<<dim3(8, 8, 4), 256>>>(
        bufA, w2, b2, bufB, 256, 256, 0, 64);
    // L3: 64->128, 128x128, split-K 2 chunks x 16 co-groups of 8
    k_clear<<<1024, 256>>>(bufA, 128 * 66 * 66);
    conv_k<64, 32, 8, true, true, false><<<dim3(4, 4, 32), 256>>>(
        bufB, w3, b3, part, 128, 128, 16, 128);
    reduce_pool<true><<<2048, 256>>>((const float4*)part, b3, bufA, 128, 64, 64, 2);
    // L4: 128->256, 64x64, split-K 4 chunks x 16 co-groups of 16
    k_clear<<<512, 256>>>(bufB, 256 * 34 * 34);
    conv_k<128, 32, 16, true, true, false><<<dim3(2, 2, 64), 256>>>(
        bufA, w4, b4, part, 64, 64, 16, 256);
    reduce_pool<true><<<1024, 256>>>((const float4*)part, b4, bufB, 256, 32, 32, 4);
    // L5: 256->256, 32x32, split-K 16 chunks x 16 co-groups of 16 -> org unpadded
    conv_k<256, 16, 16, true, true, false><<<dim3(1, 1, 256), 256>>>(
        bufB, w5, b5, part, 32, 32, 16, 256);
    reduce_pool<false><<<256, 256>>>((const float4*)part, b5, bufA, 256, 16, 16, 16);
    // org = bufA (256 x 256)

    // graph stage
    k_zero<<<256, 256>>>();
    k_build_adj<<<16, 256>>>(ei);
    k_agg<<<256, 256>>>(bufA);
    k_ssoft<<<256, 128>>>(s2wl, s2wr, s2b, bufA);
    k_x1<<<2, 256>>>(s1wl, s1wr, s1b, bufA);
    k_xpool<<<1, 256>>>(dout);
    k_tmp<<<256, 128>>>();
    k_adjpool<<<128, 128>>>();
    k_link<<<256, 256>>>();
    k_ebin<<<128, 128>>>(dout);
    k_final<<<1, 128>>>(s3wl, s3wr, s3b, dout);
}

// round 5
// speedup vs baseline: 2.9212x; 1.1493x over previous
#include <cuda_runtime.h>
#include <cuda_bf16.h>
#include <math.h>
#include <stdint.h>

#define NNODE 256
#define NCLUS 128
#define NEDGE 4096
#define MARGIN 32768   // bf16 elems of slack on both sides of activation planes

// ---------------------------------------------------------------------------
// Scratch (device globals)
// ---------------------------------------------------------------------------
__device__ __align__(16) __nv_bfloat16 g_a1h[2228224];
__device__ __align__(16) __nv_bfloat16 g_a1m[2228224];
__device__ __align__(16) __nv_bfloat16 g_a2h[2228224];
__device__ __align__(16) __nv_bfloat16 g_a2m[2228224];
__device__ __align__(16) __nv_bfloat16 g_wph[600000];
__device__ __align__(16) __nv_bfloat16 g_wpm[600000];
__device__ __align__(16) float g_D[66688 * 64];     // GEMM out (max rows*cols)
__device__ float g_org[NNODE * NNODE];
__device__ float g_adj[NNODE * NNODE];
__device__ float g_agg[NNODE * NNODE];
__device__ float g_ssoft[NNODE * NCLUS];
__device__ float g_x1[NNODE * 2];
__device__ float g_tmp[NNODE * NCLUS];
__device__ float g_adjpool[NCLUS * NCLUS];
__device__ float g_nodes[NCLUS * 2];
__device__ float g_ebin[NCLUS * NCLUS];
__device__ float g_scal[2];

__global__ void k_clear(float* __restrict__ p, int n) {
    for (int i = blockIdx.x * blockDim.x + threadIdx.x; i < n;
         i += gridDim.x * blockDim.x)
        p[i] = 0.f;
}

// ---------------------------------------------------------------------------
// Warp MMA helpers (plain PTX; works on sm_100 non-'a' target)
// ---------------------------------------------------------------------------
__device__ __forceinline__ void ldsm4(uint32_t* r, uint32_t a) {
    asm volatile("ldmatrix.sync.aligned.m8n8.x4.shared.b16 {%0,%1,%2,%3}, [%4];"
                 : "=r"(r[0]), "=r"(r[1]), "=r"(r[2]), "=r"(r[3]) : "r"(a));
}
__device__ __forceinline__ void mma16816(float* d, const uint32_t* a,
                                         uint32_t b0, uint32_t b1) {
    asm volatile(
        "mma.sync.aligned.m16n8k16.row.col.f32.bf16.bf16.f32 "
        "{%0,%1,%2,%3}, {%4,%5,%6,%7}, {%8,%9}, {%0,%1,%2,%3};"
        : "+f"(d[0]), "+f"(d[1]), "+f"(d[2]), "+f"(d[3])
        : "r"(a[0]), "r"(a[1]), "r"(a[2]), "r"(a[3]), "r"(b0), "r"(b1));
}
__device__ __forceinline__ uint32_t s2u(const void* p) {
    uint32_t a;
    asm("{ .reg .u64 t; cvta.to.shared.u64 t, %1; cvt.u32.u64 %0, t; }"
        : "=r"(a) : "l"(p));
    return a;
}

// ---------------------------------------------------------------------------
// L1: direct conv 3->32, 512x512, fused bias+relu+pool, padded HWC h/m out
// ---------------------------------------------------------------------------
__global__ void __launch_bounds__(256, 2)
conv1_k(const float* __restrict__ in, const float* __restrict__ w,
        const float* __restrict__ bias,
        __nv_bfloat16* __restrict__ oh, __nv_bfloat16* __restrict__ om) {
    const int H = 512, W = 512;
    __shared__ float s_in[3 * 1156];
    __shared__ float s_w[3 * 16 * 12];
    const int tid = threadIdx.x, tx = tid & 15, ty = tid >> 4;
    const int ox0 = blockIdx.x * 16, oy0 = blockIdx.y * 16;
    const int co0 = blockIdx.z * 16;
    const int ix0 = 2 * ox0 - 1, iy0 = 2 * oy0 - 1;

    for (int i = tid; i < 16 * 27; i += 256) {
        int co = i / 27, rem = i - co * 27, ci = rem / 9, t = rem - ci * 9;
        s_w[(ci * 16 + co) * 12 + t] = w[((co0 + co) * 3 + ci) * 9 + t];
    }
    for (int ci = 0; ci < 3; ++ci) {
        const float* inp = in + ci * H * W;
        for (int i = tid; i < 1156; i += 256) {
            int r = i / 34, c = i - r * 34;
            int gy = iy0 + r, gx = ix0 + c;
            s_in[ci * 1156 + i] =
                (gy >= 0 && gy < H && gx >= 0 && gx < W) ? inp[gy * W + gx] : 0.f;
        }
    }
    __syncthreads();

    float acc[16][4];
#pragma unroll
    for (int co = 0; co < 16; ++co)
#pragma unroll
        for (int q = 0; q < 4; ++q) acc[co][q] = 0.f;

    const int base = (2 * ty) * 34 + 2 * tx;
#pragma unroll
    for (int ci = 0; ci < 3; ++ci) {
        float p[16];
        const float* sp = s_in + ci * 1156 + base;
#pragma unroll
        for (int r = 0; r < 4; ++r)
#pragma unroll
            for (int c = 0; c < 4; ++c) p[r * 4 + c] = sp[r * 34 + c];
#pragma unroll
        for (int co = 0; co < 16; ++co) {
            const float* wp = &s_w[(ci * 16 + co) * 12];
#pragma unroll
            for (int ky = 0; ky < 3; ++ky)
#pragma unroll
                for (int kx = 0; kx < 3; ++kx) {
                    float wv = wp[ky * 3 + kx];
#pragma unroll
                    for (int dy = 0; dy < 2; ++dy)
#pragma unroll
                        for (int dx = 0; dx < 2; ++dx)
                            acc[co][dy * 2 + dx] += wv * p[(dy + ky) * 4 + (dx + kx)];
                }
        }
    }

    const long pix = ((long)(oy0 + ty + 1) * 258 + (ox0 + tx + 1)) * 32;
#pragma unroll
    for (int co = 0; co < 16; ++co) {
        float m = fmaxf(fmaxf(acc[co][0], acc[co][1]),
                        fmaxf(acc[co][2], acc[co][3]));
        float v = fmaxf(m + bias[co0 + co], 0.f);
        __nv_bfloat16 h = __float2bfloat16(v);
        oh[pix + co0 + co] = h;
        om[pix + co0 + co] = __float2bfloat16(v - __bfloat162float(h));
    }
}

// ---------------------------------------------------------------------------
// Weight pack: w[co][ci][3][3] -> Wpack[co][kc], kc = k*CIN+ci (K = 9*CIN)
// ---------------------------------------------------------------------------
template <int CIN, int LGC>
__global__ void k_pack(const float* __restrict__ w, int cout,
                       __nv_bfloat16* __restrict__ wh,
                       __nv_bfloat16* __restrict__ wm) {
    constexpr int KTOT = 9 * CIN;
    int idx = blockIdx.x * 256 + threadIdx.x;
    if (idx >= cout * KTOT) return;
    int co = idx / KTOT, kc = idx - co * KTOT;
    int k = kc >> LGC, ci = kc & (CIN - 1);
    float v = w[((size_t)co * CIN + ci) * 9 + k];
    __nv_bfloat16 h = __float2bfloat16(v);
    wh[idx] = h;
    wm[idx] = __float2bfloat16(v - __bfloat162float(h));
}

// ---------------------------------------------------------------------------
// Implicit-GEMM conv via mma.sync bf16 (hi/mid x3 split):
//   D[p, co] = sum_kc A[p,kc] * W[co,kc]
// Block 256 thr = 8 warps; tile M=128, N=64; K-chunks of 32.
// Smem rows stride 80B -> conflict-free ldmatrix, no swizzle.
// ---------------------------------------------------------------------------
template <int CIN, int LGC>
__global__ void __launch_bounds__(256, 1)
gemm_conv(const __nv_bfloat16* __restrict__ ah, const __nv_bfloat16* __restrict__ am,
          const __nv_bfloat16* __restrict__ wh, const __nv_bfloat16* __restrict__ wm,
          float* __restrict__ dout, int Wp, int coutTot) {
    constexpr int KTOT = 9 * CIN;
    constexpr int NCHUNK = KTOT / 32;
    constexpr int ASZ = 128 * 80, BSZ = 64 * 80;
    constexpr int STG = 2 * ASZ + 2 * BSZ;   // 30720 per stage

    extern __shared__ __align__(16) char smc[];
    const uint32_t sb = s2u(smc);
    const int tid = threadIdx.x, lid = tid & 31, wid = tid >> 5;
    const int wmi = wid & 3, wni = wid >> 2;
    const int p0 = blockIdx.x * 128, n0 = blockIdx.y * 64;

    // loader-invariant coords: A units idx = tid (+256), B unit idx = tid
    const int arow = tid >> 2, au = tid & 3;
    const int brow = tid >> 2, bu = tid & 3;
    const uint32_t soA = arow * 80 + au * 16;
    const uint32_t soB = brow * 80 + bu * 16;

    // ldmatrix lane address components
    const int mat = lid >> 3, i8 = lid & 7;
    const int mrow0 = wmi * 32 + (mat & 1) * 8 + i8;        // mtile 0
    const int nrow0 = wni * 32 + (mat & 1) * 8 + i8;        // ntile 0
    const int cu = mat >> 1;                                 // 16B col of 8x8

    float acc[2][4][4];
#pragma unroll
    for (int t = 0; t < 2; ++t)
#pragma unroll
        for (int j = 0; j < 4; ++j)
#pragma unroll
            for (int q = 0; q < 4; ++q) acc[t][j][q] = 0.f;

    uint4 rg[6];
    auto fetch = [&](int chunk) {
        const int kc0 = chunk * 32;
        const int kc = kc0 + au * 8;
        const int k = kc >> LGC;
        const int ci = kc & (CIN - 1);
        const long off = ((long)(p0 + arow) + (k / 3 - 1) * Wp + (k % 3 - 1)) *
                             (long)CIN + ci;
        rg[0] = *(const uint4*)(ah + off);
        rg[1] = *(const uint4*)(am + off);
        rg[2] = *(const uint4*)(ah + off + 64L * CIN);
        rg[3] = *(const uint4*)(am + off + 64L * CIN);
        const long woff = (long)(n0 + brow) * KTOT + kc0 + bu * 8;
        rg[4] = *(const uint4*)(wh + woff);
        rg[5] = *(const uint4*)(wm + woff);
    };
    auto store = [&](int s) {
        char* d = smc + s * STG;
        *(uint4*)(d + soA) = rg[0];
        *(uint4*)(d + ASZ + soA) = rg[1];
        *(uint4*)(d + soA + 64 * 80) = rg[2];
        *(uint4*)(d + ASZ + soA + 64 * 80) = rg[3];
        *(uint4*)(d + 2 * ASZ + soB) = rg[4];
        *(uint4*)(d + 2 * ASZ + BSZ + soB) = rg[5];
    };
    auto compute = [&](int s) {
        const uint32_t base = sb + s * STG;
#pragma unroll
        for (int ks = 0; ks < 2; ++ks) {
            const uint32_t ucol = (ks * 2 + cu) * 16;
            uint32_t fah[2][4], fam[2][4], fbh[2][4], fbm[2][4];
#pragma unroll
            for (int t = 0; t < 2; ++t) {
                uint32_t ra = base + (mrow0 + t * 16) * 80 + ucol;
                ldsm4(fah[t], ra);
                ldsm4(fam[t], ra + ASZ);
            }
#pragma unroll
            for (int j = 0; j < 2; ++j) {
                uint32_t rb = base + 2 * ASZ + (nrow0 + j * 16) * 80 + ucol;
                ldsm4(fbh[j], rb);
                ldsm4(fbm[j], rb + BSZ);
            }
#pragma unroll
            for (int t = 0; t < 2; ++t)
#pragma unroll
                for (int j = 0; j < 2; ++j)
#pragma unroll
                    for (int sbi = 0; sbi < 2; ++sbi) {
                        float* d = acc[t][j * 2 + sbi];
                        mma16816(d, fah[t], fbh[j][sbi], fbh[j][sbi + 2]);
                        mma16816(d, fah[t], fbm[j][sbi], fbm[j][sbi + 2]);
                        mma16816(d, fam[t], fbh[j][sbi], fbh[j][sbi + 2]);
                    }
        }
    };

    fetch(0);
    store(0);
    __syncthreads();
    for (int c = 0; c < NCHUNK; ++c) {
        const bool more = (c + 1 < NCHUNK);
        if (more) fetch(c + 1);
        compute(c & 1);
        if (more) store((c + 1) & 1);
        __syncthreads();
    }

    // epilogue: write fp32 pre-pool D
    const int r = lid >> 2, cq = (lid & 3) * 2;
#pragma unroll
    for (int t = 0; t < 2; ++t) {
        const long row = p0 + wmi * 32 + t * 16 + r;
#pragma unroll
        for (int j = 0; j < 4; ++j) {
            float* bp = dout + row * coutTot + n0 + wni * 32 + j * 8 + cq;
            *(float2*)bp = make_float2(acc[t][j][0], acc[t][j][1]);
            *(float2*)(bp + 8L * coutTot) = make_float2(acc[t][j][2], acc[t][j][3]);
        }
    }
}

// ---------------------------------------------------------------------------
// Epilogues
// ---------------------------------------------------------------------------
__global__ void k_pool(const float* __restrict__ D, const float* __restrict__ bias,
                       __nv_bfloat16* __restrict__ oh, __nv_bfloat16* __restrict__ om,
                       int W2, int C2, int Wp1) {
    int idx = blockIdx.x * 256 + threadIdx.x;
    int total = W2 * W2 * C2;
    if (idx >= total) return;
    int co = idx % C2;
    int rest = idx / C2;
    int x = rest % W2, y = rest / W2;
    long p11 = (long)(2 * y + 1) * Wp1 + (2 * x + 1);
    const float* d0 = D + p11 * C2 + co;
    long dn = (long)Wp1 * C2;
    float v = fmaxf(fmaxf(d0[0], d0[C2]), fmaxf(d0[dn], d0[dn + C2]));
    float r = fmaxf(v + bias[co], 0.f);
    long oidx = ((long)(y + 1) * (W2 + 2) + (x + 1)) * C2 + co;
    __nv_bfloat16 h = __float2bfloat16(r);
    oh[oidx] = h;
    om[oidx] = __float2bfloat16(r - __bfloat162float(h));
}

__global__ void k_orgout(const float* __restrict__ D, const float* __restrict__ bias,
                         float* __restrict__ org) {
    int idx = blockIdx.x * 256 + threadIdx.x;  // 65536
    int co = idx >> 8, pp = idx & 255, y = pp >> 4, x = pp & 15;
    long p11 = (long)(2 * y + 1) * 34 + (2 * x + 1);
    const float* d0 = D + p11 * 256 + co;
    float v = fmaxf(fmaxf(d0[0], d0[256]), fmaxf(d0[34 * 256], d0[34 * 256 + 256]));
    org[idx] = fmaxf(v + bias[co], 0.f);
}

// ---------------------------------------------------------------------------
// Graph stage (verified R1-R3)
// ---------------------------------------------------------------------------
__global__ void k_zero() {
    int i = blockIdx.x * blockDim.x + threadIdx.x;
    g_adj[i] = 0.f;
    if (i < 2) g_scal[i] = 0.f;
}

__global__ void k_build_adj(const int* __restrict__ ei) {
    int e = blockIdx.x * blockDim.x + threadIdx.x;
    if (e < NEDGE)
        atomicAdd(&g_adj[ei[e] * NNODE + ei[NEDGE + e]], 1.f);
}

__global__ void __launch_bounds__(256) k_agg(const float* __restrict__ org) {
    int d = blockIdx.x, f = threadIdx.x;
    float tot = 0.f, cnt = 0.f;
    for (int s = 0; s < NNODE; ++s) {
        float a = g_adj[s * NNODE + d];
        tot += a * org[s * NNODE + f];
        cnt += a;
    }
    g_agg[d * NNODE + f] = (cnt > 0.f) ? tot / cnt : 0.f;
}

__global__ void __launch_bounds__(128) k_ssoft(const float* __restrict__ wl,
                                               const float* __restrict__ wr,
                                               const float* __restrict__ bb,
                                               const float* __restrict__ org) {
    int i = blockIdx.x, j = threadIdx.x;
    const float* aggr = &g_agg[i * NNODE];
    const float* orgr = org + i * NNODE;
    float v = bb[j];
    for (int k = 0; k < NNODE; ++k)
        v += aggr[k] * wl[k * NCLUS + j] + orgr[k] * wr[k * NCLUS + j];

    __shared__ float red[128];
    red[j] = v; __syncthreads();
    for (int off = 64; off > 0; off >>= 1) {
        if (j < off) red[j] = fmaxf(red[j], red[j + off]);
        __syncthreads();
    }
    float m = red[0]; __syncthreads();
    float e = expf(v - m);
    red[j] = e; __syncthreads();
    for (int off = 64; off > 0; off >>= 1) {
        if (j < off) red[j] += red[j + off];
        __syncthreads();
    }
    float p = e / red[0];
    g_ssoft[i * NCLUS + j] = p;
    float ent = -p * logf(p + 1e-15f);
    __syncthreads();
    red[j] = ent; __syncthreads();
    for (int off = 64; off > 0; off >>= 1) {
        if (j < off) red[j] += red[j + off];
        __syncthreads();
    }
    if (j == 0) atomicAdd(&g_scal[1], red[0]);
}

__global__ void __launch_bounds__(256) k_x1(const float* __restrict__ wl,
                                            const float* __restrict__ wr,
                                            const float* __restrict__ bb,
                                            const float* __restrict__ org) {
    int t = blockIdx.x * 256 + threadIdx.x;
    int i = t >> 1, j = t & 1;
    float v = bb[j];
    const float* aggr = &g_agg[i * NNODE];
    const float* orgr = org + i * NNODE;
    for (int k = 0; k < NNODE; ++k)
        v += aggr[k] * wl[k * 2 + j] + orgr[k] * wr[k * 2 + j];
    g_x1[i * 2 + j] = v;
}

__global__ void __launch_bounds__(256) k_xpool(float* __restrict__ dout) {
    int t = threadIdx.x;
    int c = t >> 1, j = t & 1;
    float v = 0.f;
    for (int i = 0; i < NNODE; ++i)
        v += g_ssoft[i * NCLUS + c] * g_x1[i * 2 + j];
    float nd = tanhf(v);
    g_nodes[c * 2 + j] = nd;
    dout[258 + c * 2 + j] = nd;
}

__global__ void __launch_bounds__(128) k_tmp() {
    int i = blockIdx.x, c = threadIdx.x;
    const float* ar = &g_adj[i * NNODE];
    float v = 0.f;
    for (int k = 0; k < NNODE; ++k) v += ar[k] * g_ssoft[k * NCLUS + c];
    g_tmp[i * NCLUS + c] = v;
}

__global__ void __launch_bounds__(128) k_adjpool() {
    int r = blockIdx.x, c = threadIdx.x;
    float v = 0.f;
    for (int i = 0; i < NNODE; ++i)
        v += g_ssoft[i * NCLUS + r] * g_tmp[i * NCLUS + c];
    g_adjpool[r * NCLUS + c] = v;
}

__global__ void __launch_bounds__(256) k_link() {
    int i = blockIdx.x, j = threadIdx.x;
    __shared__ float rowi[128];
    if (j < 128) rowi[j] = g_ssoft[i * NCLUS + j];
    __syncthreads();
    float d = 0.f;
    const float* rj = &g_ssoft[j * NCLUS];
    for (int c = 0; c < NCLUS; ++c) d += rowi[c] * rj[c];
    float diff = g_adj[i * NNODE + j] - d;
    float sq = diff * diff;
    __shared__ float red[256];
    red[j] = sq; __syncthreads();
    for (int off = 128; off > 0; off >>= 1) {
        if (j < off) red[j] += red[j + off];
        __syncthreads();
    }
    if (j == 0) atomicAdd(&g_scal[0], red[0]);
}

__global__ void __launch_bounds__(128) k_ebin(float* __restrict__ dout) {
    int r = blockIdx.x, c = threadIdx.x;
    float v = g_adjpool[r * NCLUS + c];
    __shared__ float red[128];
    red[c] = v; __syncthreads();
    for (int off = 64; off > 0; off >>= 1) {
        if (c < off) red[c] = fmaxf(red[c], red[c + off]);
        __syncthreads();
    }
    float eb = (v == red[0]) ? 1.f : 0.f;
    g_ebin[r * NCLUS + c] = eb;
    dout[514 + r * NCLUS + c] = eb;
}

__global__ void __launch_bounds__(128) k_final(const float* __restrict__ wl,
                                               const float* __restrict__ wr,
                                               const float* __restrict__ bb,
                                               float* __restrict__ dout) {
    int c = threadIdx.x;
    float ind = 0.f, a0 = 0.f, a1 = 0.f;
    for (int r = 0; r < NCLUS; ++r) {
        float e = g_ebin[r * NCLUS + c];
        ind += e;
        a0 += e * g_nodes[r * 2];
        a1 += e * g_nodes[r * 2 + 1];
    }
    if (ind > 0.f) { a0 /= ind; a1 /= ind; } else { a0 = 0.f; a1 = 0.f; }
    float n0 = g_nodes[c * 2], n1 = g_nodes[c * 2 + 1];
#pragma unroll
    for (int j = 0; j < 2; ++j) {
        float o = a0 * wl[j] + a1 * wl[2 + j] + bb[j] + n0 * wr[j] + n1 * wr[2 + j];
        dout[c * 2 + j] = o;
    }
    if (c == 0) {
        dout[256] = sqrtf(g_scal[0]) / 65536.f;
        dout[257] = g_scal[1] / 256.f;
    }
}

// ---------------------------------------------------------------------------
extern "C" void kernel_launch(void* const* d_in, const int* in_sizes, int n_in,
                              void* d_out, int out_size) {
    const float* x    = (const float*)d_in[0];
    const int*   ei   = (const int*)d_in[1];
    const float* w1   = (const float*)d_in[2];
    const float* b1   = (const float*)d_in[3];
    const float* w2   = (const float*)d_in[4];
    const float* b2   = (const float*)d_in[5];
    const float* w3   = (const float*)d_in[6];
    const float* b3   = (const float*)d_in[7];
    const float* w4   = (const float*)d_in[8];
    const float* b4   = (const float*)d_in[9];
    const float* w5   = (const float*)d_in[10];
    const float* b5   = (const float*)d_in[11];
    const float* s1wl = (const float*)d_in[12];
    const float* s1wr = (const float*)d_in[13];
    const float* s1b  = (const float*)d_in[14];
    const float* s2wl = (const float*)d_in[15];
    const float* s2wr = (const float*)d_in[16];
    const float* s2b  = (const float*)d_in[17];
    const float* s3wl = (const float*)d_in[18];
    const float* s3wr = (const float*)d_in[19];
    const float* s3b  = (const float*)d_in[20];
    float* dout = (float*)d_out;

    __nv_bfloat16 *a1h, *a1m, *a2h, *a2m, *wph, *wpm;
    float *D, *org;
    cudaGetSymbolAddress((void**)&a1h, g_a1h);
    cudaGetSymbolAddress((void**)&a1m, g_a1m);
    cudaGetSymbolAddress((void**)&a2h, g_a2h);
    cudaGetSymbolAddress((void**)&a2m, g_a2m);
    cudaGetSymbolAddress((void**)&wph, g_wph);
    cudaGetSymbolAddress((void**)&wpm, g_wpm);
    cudaGetSymbolAddress((void**)&D, g_D);
    cudaGetSymbolAddress((void**)&org, g_org);

    const int SMEM = 2 * (2 * 128 * 80 + 2 * 64 * 80);   // 61440
    cudaFuncSetAttribute(gemm_conv<32, 5>,
                         cudaFuncAttributeMaxDynamicSharedMemorySize, SMEM);
    cudaFuncSetAttribute(gemm_conv<64, 6>,
                         cudaFuncAttributeMaxDynamicSharedMemorySize, SMEM);
    cudaFuncSetAttribute(gemm_conv<128, 7>,
                         cudaFuncAttributeMaxDynamicSharedMemorySize, SMEM);
    cudaFuncSetAttribute(gemm_conv<256, 8>,
                         cudaFuncAttributeMaxDynamicSharedMemorySize, SMEM);

    // zero activation buffers (margins + pad rings must be 0)
    k_clear<<<2048, 256>>>((float*)a1h, 1114112);
    k_clear<<<2048, 256>>>((float*)a1m, 1114112);
    k_clear<<<2048, 256>>>((float*)a2h, 1114112);
    k_clear<<<2048, 256>>>((float*)a2m, 1114112);

    // L1 direct conv -> a1 (258-grid, C=32)
    conv1_k<<<dim3(16, 16, 2), 256>>>(x, w1, b1, a1h + MARGIN, a1m + MARGIN);

    // L2: 32->64 @256 grid(258), K=288 -> a2 (130-grid, C=64)
    k_pack<32, 5><<<72, 256>>>(w2, 64, wph, wpm);
    gemm_conv<32, 5><<<dim3(521, 1), 256, SMEM>>>(
        a1h + MARGIN, a1m + MARGIN, wph, wpm, D, 258, 64);
    k_pool<<<4096, 256>>>(D, b2, a2h + MARGIN, a2m + MARGIN, 128, 64, 258);

    // re-zero a1 plane for the 66-grid reuse (pad ring must be 0)
    k_clear<<<512, 256>>>((float*)a1h + MARGIN / 2, 278784);
    k_clear<<<512, 256>>>((float*)a1m + MARGIN / 2, 278784);

    // L3: 64->128 @128 grid(130), K=576 -> a1 (66-grid, C=128)
    k_pack<64, 6><<<288, 256>>>(w3, 128, wph, wpm);
    gemm_conv<64, 6><<<dim3(133, 2), 256, SMEM>>>(
        a2h + MARGIN, a2m + MARGIN, wph, wpm, D, 130, 128);
    k_pool<<<2048, 256>>>(D, b3, a1h + MARGIN, a1m + MARGIN, 64, 128, 130);

    // re-zero a2 plane for the 34-grid reuse
    k_clear<<<512, 256>>>((float*)a2h + MARGIN / 2, 147968);
    k_clear<<<512, 256>>>((float*)a2m + MARGIN / 2, 147968);

    // L4: 128->256 @64 grid(66), K=1152 -> a2 (34-grid, C=256)
    k_pack<128, 7><<<1152, 256>>>(w4, 256, wph, wpm);
    gemm_conv<128, 7><<<dim3(35, 4), 256, SMEM>>>(
        a1h + MARGIN, a1m + MARGIN, wph, wpm, D, 66, 256);
    k_pool<<<1024, 256>>>(D, b4, a2h + MARGIN, a2m + MARGIN, 32, 256, 66);

    // L5: 256->256 @32 grid(34), K=2304 -> org (channel-major fp32)
    k_pack<256, 8><<<2304, 256>>>(w5, 256, wph, wpm);
    gemm_conv<256, 8><<<dim3(10, 4), 256, SMEM>>>(
        a2h + MARGIN, a2m + MARGIN, wph, wpm, D, 34, 256);
    k_orgout<<<256, 256>>>(D, b5, org);

    // graph stage
    k_zero<<<256, 256>>>();
    k_build_adj<<<16, 256>>>(ei);
    k_agg<<<256, 256>>>(org);
    k_ssoft<<<256, 128>>>(s2wl, s2wr, s2b, org);
    k_x1<<<2, 256>>>(s1wl, s1wr, s1b, org);
    k_xpool<<<1, 256>>>(dout);
    k_tmp<<<256, 128>>>();
    k_adjpool<<<128, 128>>>();
    k_link<<<256, 256>>>();
    k_ebin<<<128, 128>>>(dout);
    k_final<<<1, 128>>>(s3wl, s3wr, s3b, dout);
}

// round 6
// speedup vs baseline: 3.4307x; 1.1744x over previous
#include <cuda_runtime.h>
#include <cuda_bf16.h>
#include <math.h>
#include <stdint.h>

#define NNODE 256
#define NCLUS 128
#define NEDGE 4096
#define MARGIN 32768   // bf16 elems of slack on both sides of activation planes

// ---------------------------------------------------------------------------
// Scratch (device globals). Zero-initialized at module load; pad rings and
// margins are NEVER written, so they stay zero across all replays.
// ---------------------------------------------------------------------------
__device__ __align__(16) __nv_bfloat16 g_a1h[2228224];  // 258^2*32 + margins
__device__ __align__(16) __nv_bfloat16 g_a1m[2228224];
__device__ __align__(16) __nv_bfloat16 g_a2h[1150000];  // 130^2*64 + margins
__device__ __align__(16) __nv_bfloat16 g_a2m[1150000];
__device__ __align__(16) __nv_bfloat16 g_a3h[625000];   // 66^2*128 + margins
__device__ __align__(16) __nv_bfloat16 g_a3m[625000];
__device__ __align__(16) __nv_bfloat16 g_a4h[365000];   // 34^2*256 + margins
__device__ __align__(16) __nv_bfloat16 g_a4m[365000];
__device__ __align__(16) __nv_bfloat16 g_wph[980000];
__device__ __align__(16) __nv_bfloat16 g_wpm[980000];
__device__ __align__(16) float g_D[66688 * 64];     // GEMM out (max rows*cols)
__device__ float g_org[NNODE * NNODE];
__device__ float g_adj[NNODE * NNODE];
__device__ float g_ssoft[NNODE * NCLUS];
__device__ float g_x1[NNODE * 2];
__device__ float g_tmp[NNODE * NCLUS];
__device__ float g_nodes[NCLUS * 2];
__device__ float g_ebin[NCLUS * NCLUS];
__device__ float g_scal[2];

// ---------------------------------------------------------------------------
// Warp MMA helpers (plain PTX; works on sm_100 non-'a' target)
// ---------------------------------------------------------------------------
__device__ __forceinline__ void ldsm4(uint32_t* r, uint32_t a) {
    asm volatile("ldmatrix.sync.aligned.m8n8.x4.shared.b16 {%0,%1,%2,%3}, [%4];"
                 : "=r"(r[0]), "=r"(r[1]), "=r"(r[2]), "=r"(r[3]) : "r"(a));
}
__device__ __forceinline__ void mma16816(float* d, const uint32_t* a,
                                         uint32_t b0, uint32_t b1) {
    asm volatile(
        "mma.sync.aligned.m16n8k16.row.col.f32.bf16.bf16.f32 "
        "{%0,%1,%2,%3}, {%4,%5,%6,%7}, {%8,%9}, {%0,%1,%2,%3};"
        : "+f"(d[0]), "+f"(d[1]), "+f"(d[2]), "+f"(d[3])
        : "r"(a[0]), "r"(a[1]), "r"(a[2]), "r"(a[3]), "r"(b0), "r"(b1));
}
__device__ __forceinline__ uint32_t s2u(const void* p) {
    uint32_t a;
    asm("{ .reg .u64 t; cvta.to.shared.u64 t, %1; cvt.u32.u64 %0, t; }"
        : "=r"(a) : "l"(p));
    return a;
}

// ---------------------------------------------------------------------------
// L1: direct conv 3->32, 512x512, fused bias+relu+pool, padded HWC h/m out
// ---------------------------------------------------------------------------
__global__ void __launch_bounds__(256, 2)
conv1_k(const float* __restrict__ in, const float* __restrict__ w,
        const float* __restrict__ bias,
        __nv_bfloat16* __restrict__ oh, __nv_bfloat16* __restrict__ om) {
    const int H = 512, W = 512;
    __shared__ float s_in[3 * 1156];
    __shared__ float s_w[3 * 16 * 12];
    const int tid = threadIdx.x, tx = tid & 15, ty = tid >> 4;
    const int ox0 = blockIdx.x * 16, oy0 = blockIdx.y * 16;
    const int co0 = blockIdx.z * 16;
    const int ix0 = 2 * ox0 - 1, iy0 = 2 * oy0 - 1;

    for (int i = tid; i < 16 * 27; i += 256) {
        int co = i / 27, rem = i - co * 27, ci = rem / 9, t = rem - ci * 9;
        s_w[(ci * 16 + co) * 12 + t] = w[((co0 + co) * 3 + ci) * 9 + t];
    }
    for (int ci = 0; ci < 3; ++ci) {
        const float* inp = in + ci * H * W;
        for (int i = tid; i < 1156; i += 256) {
            int r = i / 34, c = i - r * 34;
            int gy = iy0 + r, gx = ix0 + c;
            s_in[ci * 1156 + i] =
                (gy >= 0 && gy < H && gx >= 0 && gx < W) ? inp[gy * W + gx] : 0.f;
        }
    }
    __syncthreads();

    float acc[16][4];
#pragma unroll
    for (int co = 0; co < 16; ++co)
#pragma unroll
        for (int q = 0; q < 4; ++q) acc[co][q] = 0.f;

    const int base = (2 * ty) * 34 + 2 * tx;
#pragma unroll
    for (int ci = 0; ci < 3; ++ci) {
        float p[16];
        const float* sp = s_in + ci * 1156 + base;
#pragma unroll
        for (int r = 0; r < 4; ++r)
#pragma unroll
            for (int c = 0; c < 4; ++c) p[r * 4 + c] = sp[r * 34 + c];
#pragma unroll
        for (int co = 0; co < 16; ++co) {
            const float* wp = &s_w[(ci * 16 + co) * 12];
#pragma unroll
            for (int ky = 0; ky < 3; ++ky)
#pragma unroll
                for (int kx = 0; kx < 3; ++kx) {
                    float wv = wp[ky * 3 + kx];
#pragma unroll
                    for (int dy = 0; dy < 2; ++dy)
#pragma unroll
                        for (int dx = 0; dx < 2; ++dx)
                            acc[co][dy * 2 + dx] += wv * p[(dy + ky) * 4 + (dx + kx)];
                }
        }
    }

    const long pix = ((long)(oy0 + ty + 1) * 258 + (ox0 + tx + 1)) * 32;
#pragma unroll
    for (int co = 0; co < 16; ++co) {
        float m = fmaxf(fmaxf(acc[co][0], acc[co][1]),
                        fmaxf(acc[co][2], acc[co][3]));
        float v = fmaxf(m + bias[co0 + co], 0.f);
        __nv_bfloat16 h = __float2bfloat16(v);
        oh[pix + co0 + co] = h;
        om[pix + co0 + co] = __float2bfloat16(v - __bfloat162float(h));
    }
}

// ---------------------------------------------------------------------------
// Fused weight pack for w2..w5: w[co][ci][3][3] -> Wpack[co][kc], kc=k*CIN+ci
// Offsets: L2@0 (18432), L3@18432 (73728), L4@92160 (294912), L5@387072 (589824)
// ---------------------------------------------------------------------------
__global__ void k_packall(const float* __restrict__ w2, const float* __restrict__ w3,
                          const float* __restrict__ w4, const float* __restrict__ w5,
                          __nv_bfloat16* __restrict__ wh,
                          __nv_bfloat16* __restrict__ wm) {
    int idx = blockIdx.x * 256 + threadIdx.x;
    if (idx >= 976896) return;
    const float* w; int CIN, LGC, base;
    if (idx < 18432)      { w = w2; CIN = 32;  LGC = 5; base = 0; }
    else if (idx < 92160) { w = w3; CIN = 64;  LGC = 6; base = 18432; }
    else if (idx < 387072){ w = w4; CIN = 128; LGC = 7; base = 92160; }
    else                  { w = w5; CIN = 256; LGC = 8; base = 387072; }
    int local = idx - base;
    int KTOT = 9 * CIN;
    int co = local / KTOT, kc = local - co * KTOT;
    int k = kc >> LGC, ci = kc & (CIN - 1);
    float v = w[((size_t)co * CIN + ci) * 9 + k];
    __nv_bfloat16 h = __float2bfloat16(v);
    wh[idx] = h;
    wm[idx] = __float2bfloat16(v - __bfloat162float(h));
}

// ---------------------------------------------------------------------------
// Implicit-GEMM conv via mma.sync bf16 (hi/mid x3 split). Verified R5.
// ---------------------------------------------------------------------------
template <int CIN, int LGC>
__global__ void __launch_bounds__(256, 1)
gemm_conv(const __nv_bfloat16* __restrict__ ah, const __nv_bfloat16* __restrict__ am,
          const __nv_bfloat16* __restrict__ wh, const __nv_bfloat16* __restrict__ wm,
          float* __restrict__ dout, int Wp, int coutTot) {
    constexpr int KTOT = 9 * CIN;
    constexpr int NCHUNK = KTOT / 32;
    constexpr int ASZ = 128 * 80, BSZ = 64 * 80;
    constexpr int STG = 2 * ASZ + 2 * BSZ;   // 30720 per stage

    extern __shared__ __align__(16) char smc[];
    const uint32_t sb = s2u(smc);
    const int tid = threadIdx.x, lid = tid & 31, wid = tid >> 5;
    const int wmi = wid & 3, wni = wid >> 2;
    const int p0 = blockIdx.x * 128, n0 = blockIdx.y * 64;

    const int arow = tid >> 2, au = tid & 3;
    const int brow = tid >> 2, bu = tid & 3;
    const uint32_t soA = arow * 80 + au * 16;
    const uint32_t soB = brow * 80 + bu * 16;

    const int mat = lid >> 3, i8 = lid & 7;
    const int mrow0 = wmi * 32 + (mat & 1) * 8 + i8;
    const int nrow0 = wni * 32 + (mat & 1) * 8 + i8;
    const int cu = mat >> 1;

    float acc[2][4][4];
#pragma unroll
    for (int t = 0; t < 2; ++t)
#pragma unroll
        for (int j = 0; j < 4; ++j)
#pragma unroll
            for (int q = 0; q < 4; ++q) acc[t][j][q] = 0.f;

    uint4 rg[6];
    auto fetch = [&](int chunk) {
        const int kc0 = chunk * 32;
        const int kc = kc0 + au * 8;
        const int k = kc >> LGC;
        const int ci = kc & (CIN - 1);
        const long off = ((long)(p0 + arow) + (k / 3 - 1) * Wp + (k % 3 - 1)) *
                             (long)CIN + ci;
        rg[0] = *(const uint4*)(ah + off);
        rg[1] = *(const uint4*)(am + off);
        rg[2] = *(const uint4*)(ah + off + 64L * CIN);
        rg[3] = *(const uint4*)(am + off + 64L * CIN);
        const long woff = (long)(n0 + brow) * KTOT + kc0 + bu * 8;
        rg[4] = *(const uint4*)(wh + woff);
        rg[5] = *(const uint4*)(wm + woff);
    };
    auto store = [&](int s) {
        char* d = smc + s * STG;
        *(uint4*)(d + soA) = rg[0];
        *(uint4*)(d + ASZ + soA) = rg[1];
        *(uint4*)(d + soA + 64 * 80) = rg[2];
        *(uint4*)(d + ASZ + soA + 64 * 80) = rg[3];
        *(uint4*)(d + 2 * ASZ + soB) = rg[4];
        *(uint4*)(d + 2 * ASZ + BSZ + soB) = rg[5];
    };
    auto compute = [&](int s) {
        const uint32_t base = sb + s * STG;
#pragma unroll
        for (int ks = 0; ks < 2; ++ks) {
            const uint32_t ucol = (ks * 2 + cu) * 16;
            uint32_t fah[2][4], fam[2][4], fbh[2][4], fbm[2][4];
#pragma unroll
            for (int t = 0; t < 2; ++t) {
                uint32_t ra = base + (mrow0 + t * 16) * 80 + ucol;
                ldsm4(fah[t], ra);
                ldsm4(fam[t], ra + ASZ);
            }
#pragma unroll
            for (int j = 0; j < 2; ++j) {
                uint32_t rb = base + 2 * ASZ + (nrow0 + j * 16) * 80 + ucol;
                ldsm4(fbh[j], rb);
                ldsm4(fbm[j], rb + BSZ);
            }
#pragma unroll
            for (int t = 0; t < 2; ++t)
#pragma unroll
                for (int j = 0; j < 2; ++j)
#pragma unroll
                    for (int sbi = 0; sbi < 2; ++sbi) {
                        float* d = acc[t][j * 2 + sbi];
                        mma16816(d, fah[t], fbh[j][sbi], fbh[j][sbi + 2]);
                        mma16816(d, fah[t], fbm[j][sbi], fbm[j][sbi + 2]);
                        mma16816(d, fam[t], fbh[j][sbi], fbh[j][sbi + 2]);
                    }
        }
    };

    fetch(0);
    store(0);
    __syncthreads();
    for (int c = 0; c < NCHUNK; ++c) {
        const bool more = (c + 1 < NCHUNK);
        if (more) fetch(c + 1);
        compute(c & 1);
        if (more) store((c + 1) & 1);
        __syncthreads();
    }

    const int r = lid >> 2, cq = (lid & 3) * 2;
#pragma unroll
    for (int t = 0; t < 2; ++t) {
        const long row = p0 + wmi * 32 + t * 16 + r;
#pragma unroll
        for (int j = 0; j < 4; ++j) {
            float* bp = dout + row * coutTot + n0 + wni * 32 + j * 8 + cq;
            *(float2*)bp = make_float2(acc[t][j][0], acc[t][j][1]);
            *(float2*)(bp + 8L * coutTot) = make_float2(acc[t][j][2], acc[t][j][3]);
        }
    }
}

// ---------------------------------------------------------------------------
// Epilogues
// ---------------------------------------------------------------------------
__global__ void k_pool(const float* __restrict__ D, const float* __restrict__ bias,
                       __nv_bfloat16* __restrict__ oh, __nv_bfloat16* __restrict__ om,
                       int W2, int C2, int Wp1) {
    int idx = blockIdx.x * 256 + threadIdx.x;
    int total = W2 * W2 * C2;
    if (idx >= total) return;
    int co = idx % C2;
    int rest = idx / C2;
    int x = rest % W2, y = rest / W2;
    long p11 = (long)(2 * y + 1) * Wp1 + (2 * x + 1);
    const float* d0 = D + p11 * C2 + co;
    long dn = (long)Wp1 * C2;
    float v = fmaxf(fmaxf(d0[0], d0[C2]), fmaxf(d0[dn], d0[dn + C2]));
    float r = fmaxf(v + bias[co], 0.f);
    long oidx = ((long)(y + 1) * (W2 + 2) + (x + 1)) * C2 + co;
    __nv_bfloat16 h = __float2bfloat16(r);
    oh[oidx] = h;
    om[oidx] = __float2bfloat16(r - __bfloat162float(h));
}

__global__ void k_orgout(const float* __restrict__ D, const float* __restrict__ bias,
                         float* __restrict__ org) {
    int idx = blockIdx.x * 256 + threadIdx.x;  // 65536
    int co = idx >> 8, pp = idx & 255, y = pp >> 4, x = pp & 15;
    long p11 = (long)(2 * y + 1) * 34 + (2 * x + 1);
    const float* d0 = D + p11 * 256 + co;
    float v = fmaxf(fmaxf(d0[0], d0[256]), fmaxf(d0[34 * 256], d0[34 * 256 + 256]));
    org[idx] = fmaxf(v + bias[co], 0.f);
}

// ---------------------------------------------------------------------------
// Graph stage
// ---------------------------------------------------------------------------
__global__ void k_zero() {
    int i = blockIdx.x * blockDim.x + threadIdx.x;
    g_adj[i] = 0.f;
    if (i < 2) g_scal[i] = 0.f;
}

__global__ void k_build_adj(const int* __restrict__ ei) {
    int e = blockIdx.x * blockDim.x + threadIdx.x;
    if (e < NEDGE)
        atomicAdd(&g_adj[ei[e] * NNODE + ei[NEDGE + e]], 1.f);
}

// Fused per-node-row stage: mean-agg row -> SAGE2+softmax+entropy -> SAGE1 (x1)
__global__ void __launch_bounds__(256)
k_rowstage(const float* __restrict__ org,
           const float* __restrict__ wl1, const float* __restrict__ wr1,
           const float* __restrict__ b1v,
           const float* __restrict__ wl2, const float* __restrict__ wr2,
           const float* __restrict__ b2v) {
    __shared__ float sAgg[256], sOrg[256], sv[256], red[128], sx[4];
    const int i = blockIdx.x, t = threadIdx.x;
    sOrg[t] = org[i * 256 + t];
    float tot = 0.f, cnt = 0.f;
    for (int s = 0; s < 256; ++s) {
        float a = g_adj[s * 256 + i];
        tot += a * org[s * 256 + t];
        cnt += a;
    }
    sAgg[t] = (cnt > 0.f) ? tot / cnt : 0.f;
    __syncthreads();

    // SAGE2 (256x128): k-range split across thread halves
    const int j = t & 127, h = t >> 7;
    float v = 0.f;
    for (int k = h * 128; k < h * 128 + 128; ++k)
        v += sAgg[k] * wl2[k * 128 + j] + sOrg[k] * wr2[k * 128 + j];
    sv[t] = v;
    __syncthreads();

    float lv = (t < 128) ? sv[t] + sv[t + 128] + b2v[t] : -1e30f;
    // SAGE1 (256x2) partials on threads 128..131
    if (t >= 128 && t < 132) {
        int jj = (t - 128) & 1, hh = (t - 128) >> 1;
        float xv = 0.f;
        for (int k = hh * 128; k < hh * 128 + 128; ++k)
            xv += sAgg[k] * wl1[k * 2 + jj] + sOrg[k] * wr1[k * 2 + jj];
        sx[t - 128] = xv;
    }

    if (t < 128) red[t] = lv;
    __syncthreads();
    for (int off = 64; off > 0; off >>= 1) {
        if (t < off) red[t] = fmaxf(red[t], red[t + off]);
        __syncthreads();
    }
    float m = red[0];
    __syncthreads();
    float e = (t < 128) ? expf(lv - m) : 0.f;
    if (t < 128) red[t] = e;
    __syncthreads();
    for (int off = 64; off > 0; off >>= 1) {
        if (t < off) red[t] += red[t + off];
        __syncthreads();
    }
    float denom = red[0];
    __syncthreads();
    float p = e / denom;
    if (t < 128) {
        g_ssoft[i * 128 + t] = p;
        red[t] = -p * logf(p + 1e-15f);
    }
    __syncthreads();
    for (int off = 64; off > 0; off >>= 1) {
        if (t < off) red[t] += red[t + off];
        __syncthreads();
    }
    if (t == 0) atomicAdd(&g_scal[1], red[0]);
    if (t < 2) g_x1[i * 2 + t] = sx[t] + sx[t + 2] + b1v[t];
}

__global__ void __launch_bounds__(128) k_tmp() {
    int i = blockIdx.x, c = threadIdx.x;
    const float* ar = &g_adj[i * NNODE];
    float v = 0.f;
    for (int k = 0; k < NNODE; ++k) v += ar[k] * g_ssoft[k * NCLUS + c];
    g_tmp[i * NCLUS + c] = v;
}

__global__ void __launch_bounds__(256) k_link() {
    int i = blockIdx.x, j = threadIdx.x;
    __shared__ float rowi[128];
    if (j < 128) rowi[j] = g_ssoft[i * NCLUS + j];
    __syncthreads();
    float d = 0.f;
    const float* rj = &g_ssoft[j * NCLUS];
    for (int c = 0; c < NCLUS; ++c) d += rowi[c] * rj[c];
    float diff = g_adj[i * NNODE + j] - d;
    float sq = diff * diff;
    __shared__ float red[256];
    red[j] = sq; __syncthreads();
    for (int off = 128; off > 0; off >>= 1) {
        if (j < off) red[j] += red[j + off];
        __syncthreads();
    }
    if (j == 0) atomicAdd(&g_scal[0], red[0]);
}

__global__ void __launch_bounds__(256) k_xpool(float* __restrict__ dout) {
    int t = threadIdx.x;
    int c = t >> 1, j = t & 1;
    float v = 0.f;
    for (int i = 0; i < NNODE; ++i)
        v += g_ssoft[i * NCLUS + c] * g_x1[i * 2 + j];
    float nd = tanhf(v);
    g_nodes[c * 2 + j] = nd;
    dout[258 + c * 2 + j] = nd;
}

// Fused: adjpool row r (ssoft^T @ tmp) -> rowmax -> edge_bin
__global__ void __launch_bounds__(128) k_adjebin(float* __restrict__ dout) {
    int r = blockIdx.x, c = threadIdx.x;
    float v = 0.f;
    for (int i = 0; i < NNODE; ++i)
        v += g_ssoft[i * NCLUS + r] * g_tmp[i * NCLUS + c];
    __shared__ float red[128];
    red[c] = v; __syncthreads();
    for (int off = 64; off > 0; off >>= 1) {
        if (c < off) red[c] = fmaxf(red[c], red[c + off]);
        __syncthreads();
    }
    float eb = (v == red[0]) ? 1.f : 0.f;
    g_ebin[r * NCLUS + c] = eb;
    dout[514 + r * NCLUS + c] = eb;
}

__global__ void __launch_bounds__(128) k_final(const float* __restrict__ wl,
                                               const float* __restrict__ wr,
                                               const float* __restrict__ bb,
                                               float* __restrict__ dout) {
    int c = threadIdx.x;
    float ind = 0.f, a0 = 0.f, a1 = 0.f;
    for (int r = 0; r < NCLUS; ++r) {
        float e = g_ebin[r * NCLUS + c];
        ind += e;
        a0 += e * g_nodes[r * 2];
        a1 += e * g_nodes[r * 2 + 1];
    }
    if (ind > 0.f) { a0 /= ind; a1 /= ind; } else { a0 = 0.f; a1 = 0.f; }
    float n0 = g_nodes[c * 2], n1 = g_nodes[c * 2 + 1];
#pragma unroll
    for (int j = 0; j < 2; ++j) {
        float o = a0 * wl[j] + a1 * wl[2 + j] + bb[j] + n0 * wr[j] + n1 * wr[2 + j];
        dout[c * 2 + j] = o;
    }
    if (c == 0) {
        dout[256] = sqrtf(g_scal[0]) / 65536.f;
        dout[257] = g_scal[1] / 256.f;
    }
}

// ---------------------------------------------------------------------------
extern "C" void kernel_launch(void* const* d_in, const int* in_sizes, int n_in,
                              void* d_out, int out_size) {
    const float* x    = (const float*)d_in[0];
    const int*   ei   = (const int*)d_in[1];
    const float* w1   = (const float*)d_in[2];
    const float* b1   = (const float*)d_in[3];
    const float* w2   = (const float*)d_in[4];
    const float* b2   = (const float*)d_in[5];
    const float* w3   = (const float*)d_in[6];
    const float* b3   = (const float*)d_in[7];
    const float* w4   = (const float*)d_in[8];
    const float* b4   = (const float*)d_in[9];
    const float* w5   = (const float*)d_in[10];
    const float* b5   = (const float*)d_in[11];
    const float* s1wl = (const float*)d_in[12];
    const float* s1wr = (const float*)d_in[13];
    const float* s1b  = (const float*)d_in[14];
    const float* s2wl = (const float*)d_in[15];
    const float* s2wr = (const float*)d_in[16];
    const float* s2b  = (const float*)d_in[17];
    const float* s3wl = (const float*)d_in[18];
    const float* s3wr = (const float*)d_in[19];
    const float* s3b  = (const float*)d_in[20];
    float* dout = (float*)d_out;

    __nv_bfloat16 *a1h, *a1m, *a2h, *a2m, *a3h, *a3m, *a4h, *a4m, *wph, *wpm;
    float *D, *org;
    cudaGetSymbolAddress((void**)&a1h, g_a1h);
    cudaGetSymbolAddress((void**)&a1m, g_a1m);
    cudaGetSymbolAddress((void**)&a2h, g_a2h);
    cudaGetSymbolAddress((void**)&a2m, g_a2m);
    cudaGetSymbolAddress((void**)&a3h, g_a3h);
    cudaGetSymbolAddress((void**)&a3m, g_a3m);
    cudaGetSymbolAddress((void**)&a4h, g_a4h);
    cudaGetSymbolAddress((void**)&a4m, g_a4m);
    cudaGetSymbolAddress((void**)&wph, g_wph);
    cudaGetSymbolAddress((void**)&wpm, g_wpm);
    cudaGetSymbolAddress((void**)&D, g_D);
    cudaGetSymbolAddress((void**)&org, g_org);

    const int SMEM = 2 * (2 * 128 * 80 + 2 * 64 * 80);   // 61440
    cudaFuncSetAttribute(gemm_conv<32, 5>,
                         cudaFuncAttributeMaxDynamicSharedMemorySize, SMEM);
    cudaFuncSetAttribute(gemm_conv<64, 6>,
                         cudaFuncAttributeMaxDynamicSharedMemorySize, SMEM);
    cudaFuncSetAttribute(gemm_conv<128, 7>,
                         cudaFuncAttributeMaxDynamicSharedMemorySize, SMEM);
    cudaFuncSetAttribute(gemm_conv<256, 8>,
                         cudaFuncAttributeMaxDynamicSharedMemorySize, SMEM);

    // weight pack (all layers, one launch)
    k_packall<<<3816, 256>>>(w2, w3, w4, w5, wph, wpm);

    // L1 direct conv -> a1 (258-grid, C=32)
    conv1_k<<<dim3(16, 16, 2), 256>>>(x, w1, b1, a1h + MARGIN, a1m + MARGIN);

    // L2: 32->64 @256 grid(258), K=288 -> a2 (130-grid, C=64)
    gemm_conv<32, 5><<<dim3(521, 1), 256, SMEM>>>(
        a1h + MARGIN, a1m + MARGIN, wph, wpm, D, 258, 64);
    k_pool<<<4096, 256>>>(D, b2, a2h + MARGIN, a2m + MARGIN, 128, 64, 258);

    // L3: 64->128 @128 grid(130), K=576 -> a3 (66-grid, C=128)
    gemm_conv<64, 6><<<dim3(133, 2), 256, SMEM>>>(
        a2h + MARGIN, a2m + MARGIN, wph + 18432, wpm + 18432, D, 130, 128);
    k_pool<<<2048, 256>>>(D, b3, a3h + MARGIN, a3m + MARGIN, 64, 128, 130);

    // L4: 128->256 @64 grid(66), K=1152 -> a4 (34-grid, C=256)
    gemm_conv<128, 7><<<dim3(35, 4), 256, SMEM>>>(
        a3h + MARGIN, a3m + MARGIN, wph + 92160, wpm + 92160, D, 66, 256);
    k_pool<<<1024, 256>>>(D, b4, a4h + MARGIN, a4m + MARGIN, 32, 256, 66);

    // L5: 256->256 @32 grid(34), K=2304 -> org (channel-major fp32)
    gemm_conv<256, 8><<<dim3(10, 4), 256, SMEM>>>(
        a4h + MARGIN, a4m + MARGIN, wph + 387072, wpm + 387072, D, 34, 256);
    k_orgout<<<256, 256>>>(D, b5, org);

    // graph stage
    k_zero<<<256, 256>>>();
    k_build_adj<<<16, 256>>>(ei);
    k_rowstage<<<256, 256>>>(org, s1wl, s1wr, s1b, s2wl, s2wr, s2b);
    k_tmp<<<256, 128>>>();
    k_link<<<256, 256>>>();
    k_xpool<<<1, 256>>>(dout);
    k_adjebin<<<128, 128>>>(dout);
    k_final<<<1, 128>>>(s3wl, s3wr, s3b, dout);
}

// round 7
// speedup vs baseline: 3.4903x; 1.0174x over previous
#include <cuda_runtime.h>
#include <cuda_bf16.h>
#include <math.h>
#include <stdint.h>

#define NNODE 256
#define NCLUS 128
#define NEDGE 4096
#define MARGIN 32768   // bf16 elems of slack on both sides of activation planes

// ---------------------------------------------------------------------------
// Scratch (device globals). Zero-initialized at module load; pad rings and
// margins are NEVER written, so they stay zero across all replays.
// ---------------------------------------------------------------------------
__device__ __align__(16) __nv_bfloat16 g_a1h[2228224];  // 258^2*32 + margins
__device__ __align__(16) __nv_bfloat16 g_a1m[2228224];
__device__ __align__(16) __nv_bfloat16 g_a2h[1150000];  // 130^2*64 + margins
__device__ __align__(16) __nv_bfloat16 g_a2m[1150000];
__device__ __align__(16) __nv_bfloat16 g_a3h[625000];   // 66^2*128 + margins
__device__ __align__(16) __nv_bfloat16 g_a3m[625000];
__device__ __align__(16) __nv_bfloat16 g_a4h[365000];   // 34^2*256 + margins
__device__ __align__(16) __nv_bfloat16 g_a4m[365000];
__device__ __align__(16) __nv_bfloat16 g_wph[980000];
__device__ __align__(16) __nv_bfloat16 g_wpm[980000];
__device__ float g_org[NNODE * NNODE];
__device__ float g_adj[NNODE * NNODE];
__device__ float g_ssoft[NNODE * NCLUS];
__device__ float g_x1[NNODE * 2];
__device__ float g_tmp[NNODE * NCLUS];
__device__ float g_nodes[NCLUS * 2];
__device__ float g_ebin[NCLUS * NCLUS];
__device__ float g_scal[2];

// ---------------------------------------------------------------------------
// Warp MMA helpers (plain PTX; works on sm_100 non-'a' target)
// ---------------------------------------------------------------------------
__device__ __forceinline__ void ldsm4(uint32_t* r, uint32_t a) {
    asm volatile("ldmatrix.sync.aligned.m8n8.x4.shared.b16 {%0,%1,%2,%3}, [%4];"
                 : "=r"(r[0]), "=r"(r[1]), "=r"(r[2]), "=r"(r[3]) : "r"(a));
}
__device__ __forceinline__ void mma16816(float* d, const uint32_t* a,
                                         uint32_t b0, uint32_t b1) {
    asm volatile(
        "mma.sync.aligned.m16n8k16.row.col.f32.bf16.bf16.f32 "
        "{%0,%1,%2,%3}, {%4,%5,%6,%7}, {%8,%9}, {%0,%1,%2,%3};"
        : "+f"(d[0]), "+f"(d[1]), "+f"(d[2]), "+f"(d[3])
        : "r"(a[0]), "r"(a[1]), "r"(a[2]), "r"(a[3]), "r"(b0), "r"(b1));
}
__device__ __forceinline__ uint32_t s2u(const void* p) {
    uint32_t a;
    asm("{ .reg .u64 t; cvta.to.shared.u64 t, %1; cvt.u32.u64 %0, t; }"
        : "=r"(a) : "l"(p));
    return a;
}

// ---------------------------------------------------------------------------
// L1: direct conv 3->32, 512x512, fused bias+relu+pool, padded HWC h/m out
// ---------------------------------------------------------------------------
__global__ void __launch_bounds__(256, 2)
conv1_k(const float* __restrict__ in, const float* __restrict__ w,
        const float* __restrict__ bias,
        __nv_bfloat16* __restrict__ oh, __nv_bfloat16* __restrict__ om) {
    const int H = 512, W = 512;
    __shared__ float s_in[3 * 1156];
    __shared__ float s_w[3 * 16 * 12];
    const int tid = threadIdx.x, tx = tid & 15, ty = tid >> 4;
    const int ox0 = blockIdx.x * 16, oy0 = blockIdx.y * 16;
    const int co0 = blockIdx.z * 16;
    const int ix0 = 2 * ox0 - 1, iy0 = 2 * oy0 - 1;

    for (int i = tid; i < 16 * 27; i += 256) {
        int co = i / 27, rem = i - co * 27, ci = rem / 9, t = rem - ci * 9;
        s_w[(ci * 16 + co) * 12 + t] = w[((co0 + co) * 3 + ci) * 9 + t];
    }
    for (int ci = 0; ci < 3; ++ci) {
        const float* inp = in + ci * H * W;
        for (int i = tid; i < 1156; i += 256) {
            int r = i / 34, c = i - r * 34;
            int gy = iy0 + r, gx = ix0 + c;
            s_in[ci * 1156 + i] =
                (gy >= 0 && gy < H && gx >= 0 && gx < W) ? inp[gy * W + gx] : 0.f;
        }
    }
    __syncthreads();

    float acc[16][4];
#pragma unroll
    for (int co = 0; co < 16; ++co)
#pragma unroll
        for (int q = 0; q < 4; ++q) acc[co][q] = 0.f;

    const int base = (2 * ty) * 34 + 2 * tx;
#pragma unroll
    for (int ci = 0; ci < 3; ++ci) {
        float p[16];
        const float* sp = s_in + ci * 1156 + base;
#pragma unroll
        for (int r = 0; r < 4; ++r)
#pragma unroll
            for (int c = 0; c < 4; ++c) p[r * 4 + c] = sp[r * 34 + c];
#pragma unroll
        for (int co = 0; co < 16; ++co) {
            const float* wp = &s_w[(ci * 16 + co) * 12];
#pragma unroll
            for (int ky = 0; ky < 3; ++ky)
#pragma unroll
                for (int kx = 0; kx < 3; ++kx) {
                    float wv = wp[ky * 3 + kx];
#pragma unroll
                    for (int dy = 0; dy < 2; ++dy)
#pragma unroll
                        for (int dx = 0; dx < 2; ++dx)
                            acc[co][dy * 2 + dx] += wv * p[(dy + ky) * 4 + (dx + kx)];
                }
        }
    }

    const long pix = ((long)(oy0 + ty + 1) * 258 + (ox0 + tx + 1)) * 32;
#pragma unroll
    for (int co = 0; co < 16; ++co) {
        float m = fmaxf(fmaxf(acc[co][0], acc[co][1]),
                        fmaxf(acc[co][2], acc[co][3]));
        float v = fmaxf(m + bias[co0 + co], 0.f);
        __nv_bfloat16 h = __float2bfloat16(v);
        oh[pix + co0 + co] = h;
        om[pix + co0 + co] = __float2bfloat16(v - __bfloat162float(h));
    }
}

// ---------------------------------------------------------------------------
// Fused weight pack for w2..w5: w[co][ci][3][3] -> Wpack[co][kc], kc=k*CIN+ci
// ---------------------------------------------------------------------------
__global__ void k_packall(const float* __restrict__ w2, const float* __restrict__ w3,
                          const float* __restrict__ w4, const float* __restrict__ w5,
                          __nv_bfloat16* __restrict__ wh,
                          __nv_bfloat16* __restrict__ wm) {
    int idx = blockIdx.x * 256 + threadIdx.x;
    if (idx >= 976896) return;
    const float* w; int CIN, LGC, base;
    if (idx < 18432)      { w = w2; CIN = 32;  LGC = 5; base = 0; }
    else if (idx < 92160) { w = w3; CIN = 64;  LGC = 6; base = 18432; }
    else if (idx < 387072){ w = w4; CIN = 128; LGC = 7; base = 92160; }
    else                  { w = w5; CIN = 256; LGC = 8; base = 387072; }
    int local = idx - base;
    int KTOT = 9 * CIN;
    int co = local / KTOT, kc = local - co * KTOT;
    int k = kc >> LGC, ci = kc & (CIN - 1);
    float v = w[((size_t)co * CIN + ci) * 9 + k];
    __nv_bfloat16 h = __float2bfloat16(v);
    wh[idx] = h;
    wm[idx] = __float2bfloat16(v - __bfloat162float(h));
}

// ---------------------------------------------------------------------------
// Implicit-GEMM conv via mma.sync bf16 (hi/mid x3 split) with FUSED
// bias+relu+maxpool epilogue.  GEMM row m maps to (pooled pixel q, quad dy/dx):
//   q = m>>2, dy = (m>>1)&1, dx = m&1 ; src pixel = (2py+1+dy, 2px+1+dx)
// OUTM=0: write pooled bf16 h/m to padded HWC plane (width W2+2)
// OUTM=1: write pooled fp32 to org (channel-major 16x16, W2==16)
// ---------------------------------------------------------------------------
template <int CIN, int LGC, int OUTM>
__global__ void __launch_bounds__(256, 1)
gemm_conv(const __nv_bfloat16* __restrict__ ah, const __nv_bfloat16* __restrict__ am,
          const __nv_bfloat16* __restrict__ wh, const __nv_bfloat16* __restrict__ wm,
          const float* __restrict__ bias,
          __nv_bfloat16* __restrict__ oh, __nv_bfloat16* __restrict__ om,
          float* __restrict__ forg,
          int Wp, int W2, int lg, int coutTot) {
    constexpr int KTOT = 9 * CIN;
    constexpr int NCHUNK = KTOT / 32;
    constexpr int ASZ = 128 * 80, BSZ = 64 * 80;
    constexpr int STG = 2 * ASZ + 2 * BSZ;   // 30720 per stage

    extern __shared__ __align__(16) char smc[];
    const uint32_t sb = s2u(smc);
    const int tid = threadIdx.x, lid = tid & 31, wid = tid >> 5;
    const int wmi = wid & 3, wni = wid >> 2;
    const int p0 = blockIdx.x * 128, n0 = blockIdx.y * 64;

    const int arow = tid >> 2, au = tid & 3;
    const uint32_t soA = arow * 80 + au * 16;
    const uint32_t soB = soA;

    const int mat = lid >> 3, i8 = lid & 7;
    const int mrow0 = wmi * 32 + (mat & 1) * 8 + i8;
    const int nrow0 = wni * 32 + (mat & 1) * 8 + i8;
    const int cu = mat >> 1;

    // row->source-pixel mapping (fixed per thread)
    auto rowbase = [&](int m) -> long {
        int q = m >> 2, dy = (m >> 1) & 1, dx = m & 1;
        int py = q >> lg, px = q & (W2 - 1);
        return ((long)(2 * py + 1 + dy) * Wp + (2 * px + 1 + dx)) * CIN;
    };
    const long rb0 = rowbase(p0 + arow);
    const long rb1 = rowbase(p0 + arow + 64);

    float acc[2][4][4];
#pragma unroll
    for (int t = 0; t < 2; ++t)
#pragma unroll
        for (int j = 0; j < 4; ++j)
#pragma unroll
            for (int q = 0; q < 4; ++q) acc[t][j][q] = 0.f;

    uint4 rg[6];
    auto fetch = [&](int chunk) {
        const int kc0 = chunk * 32;
        const int kc = kc0 + au * 8;
        const int k = kc >> LGC;
        const int ci = kc & (CIN - 1);
        const long nb = ((long)(k / 3 - 1) * Wp + (k % 3 - 1)) * CIN + ci;
        rg[0] = *(const uint4*)(ah + rb0 + nb);
        rg[1] = *(const uint4*)(am + rb0 + nb);
        rg[2] = *(const uint4*)(ah + rb1 + nb);
        rg[3] = *(const uint4*)(am + rb1 + nb);
        const long woff = (long)(n0 + arow) * KTOT + kc0 + au * 8;
        rg[4] = *(const uint4*)(wh + woff);
        rg[5] = *(const uint4*)(wm + woff);
    };
    auto store = [&](int s) {
        char* d = smc + s * STG;
        *(uint4*)(d + soA) = rg[0];
        *(uint4*)(d + ASZ + soA) = rg[1];
        *(uint4*)(d + soA + 64 * 80) = rg[2];
        *(uint4*)(d + ASZ + soA + 64 * 80) = rg[3];
        *(uint4*)(d + 2 * ASZ + soB) = rg[4];
        *(uint4*)(d + 2 * ASZ + BSZ + soB) = rg[5];
    };
    auto compute = [&](int s) {
        const uint32_t base = sb + s * STG;
#pragma unroll
        for (int ks = 0; ks < 2; ++ks) {
            const uint32_t ucol = (ks * 2 + cu) * 16;
            uint32_t fah[2][4], fam[2][4], fbh[2][4], fbm[2][4];
#pragma unroll
            for (int t = 0; t < 2; ++t) {
                uint32_t ra = base + (mrow0 + t * 16) * 80 + ucol;
                ldsm4(fah[t], ra);
                ldsm4(fam[t], ra + ASZ);
            }
#pragma unroll
            for (int j = 0; j < 2; ++j) {
                uint32_t rb = base + 2 * ASZ + (nrow0 + j * 16) * 80 + ucol;
                ldsm4(fbh[j], rb);
                ldsm4(fbm[j], rb + BSZ);
            }
#pragma unroll
            for (int t = 0; t < 2; ++t)
#pragma unroll
                for (int j = 0; j < 2; ++j)
#pragma unroll
                    for (int sbi = 0; sbi < 2; ++sbi) {
                        float* d = acc[t][j * 2 + sbi];
                        mma16816(d, fah[t], fbh[j][sbi], fbh[j][sbi + 2]);
                        mma16816(d, fah[t], fbm[j][sbi], fbm[j][sbi + 2]);
                        mma16816(d, fam[t], fbh[j][sbi], fbh[j][sbi + 2]);
                    }
        }
    };

    fetch(0);
    store(0);
    __syncthreads();
    for (int c = 0; c < NCHUNK; ++c) {
        const bool more = (c + 1 < NCHUNK);
        if (more) fetch(c + 1);
        compute(c & 1);
        if (more) store((c + 1) & 1);
        __syncthreads();
    }

    // fused epilogue: pool over 4 consecutive GEMM rows (one 2x2 quad),
    // then bias+relu and write pooled outputs.
    const int cq = (lid & 3) * 2;
    const bool wlane = (lid & 12) == 0;      // lanes with row-part r in {0,4}
    const int qsub = lid >> 4;               // 0 for r=0, 1 for r=4
#pragma unroll
    for (int j = 0; j < 4; ++j) {
        const int co = n0 + wni * 32 + j * 8 + cq;
        const float b0 = bias[co], b1 = bias[co + 1];
#pragma unroll
        for (int t = 0; t < 2; ++t) {
            float v[4];
#pragma unroll
            for (int q = 0; q < 4; ++q) {
                float x = acc[t][j][q];
                x = fmaxf(x, __shfl_xor_sync(0xffffffffu, x, 4));
                x = fmaxf(x, __shfl_xor_sync(0xffffffffu, x, 8));
                v[q] = x;
            }
            if (wlane) {
                const int Pb = (p0 >> 2) + wmi * 8 + t * 4 + qsub;
                float r0 = fmaxf(v[0] + b0, 0.f);
                float r1 = fmaxf(v[1] + b1, 0.f);
                float r2 = fmaxf(v[2] + b0, 0.f);
                float r3 = fmaxf(v[3] + b1, 0.f);
                if (OUTM == 0) {
                    int py = Pb >> lg, px = Pb & (W2 - 1);
                    long o = ((long)(py + 1) * (W2 + 2) + px + 1) * coutTot + co;
                    __nv_bfloat16 h0 = __float2bfloat16(r0);
                    __nv_bfloat16 h1 = __float2bfloat16(r1);
                    oh[o] = h0; om[o] = __float2bfloat16(r0 - __bfloat162float(h0));
                    oh[o + 1] = h1; om[o + 1] = __float2bfloat16(r1 - __bfloat162float(h1));
                    int P2 = Pb + 2;
                    int py2 = P2 >> lg, px2 = P2 & (W2 - 1);
                    long o2 = ((long)(py2 + 1) * (W2 + 2) + px2 + 1) * coutTot + co;
                    __nv_bfloat16 h2 = __float2bfloat16(r2);
                    __nv_bfloat16 h3 = __float2bfloat16(r3);
                    oh[o2] = h2; om[o2] = __float2bfloat16(r2 - __bfloat162float(h2));
                    oh[o2 + 1] = h3; om[o2 + 1] = __float2bfloat16(r3 - __bfloat162float(h3));
                } else {
                    forg[co * 256 + Pb] = r0;
                    forg[(co + 1) * 256 + Pb] = r1;
                    forg[co * 256 + Pb + 2] = r2;
                    forg[(co + 1) * 256 + Pb + 2] = r3;
                }
            }
        }
    }
}

// ---------------------------------------------------------------------------
// Graph stage
// ---------------------------------------------------------------------------
__global__ void k_zero() {
    int i = blockIdx.x * blockDim.x + threadIdx.x;
    g_adj[i] = 0.f;
    if (i < 2) g_scal[i] = 0.f;
}

__global__ void k_build_adj(const int* __restrict__ ei) {
    int e = blockIdx.x * blockDim.x + threadIdx.x;
    if (e < NEDGE)
        atomicAdd(&g_adj[ei[e] * NNODE + ei[NEDGE + e]], 1.f);
}

// Fused per-node-row stage: mean-agg row -> SAGE2+softmax+entropy -> SAGE1 (x1)
__global__ void __launch_bounds__(256)
k_rowstage(const float* __restrict__ org,
           const float* __restrict__ wl1, const float* __restrict__ wr1,
           const float* __restrict__ b1v,
           const float* __restrict__ wl2, const float* __restrict__ wr2,
           const float* __restrict__ b2v) {
    __shared__ float sAgg[256], sOrg[256], sv[256], red[128], sx[4];
    const int i = blockIdx.x, t = threadIdx.x;
    sOrg[t] = org[i * 256 + t];
    float tot = 0.f, cnt = 0.f;
    for (int s = 0; s < 256; ++s) {
        float a = g_adj[s * 256 + i];
        tot += a * org[s * 256 + t];
        cnt += a;
    }
    sAgg[t] = (cnt > 0.f) ? tot / cnt : 0.f;
    __syncthreads();

    const int j = t & 127, h = t >> 7;
    float v = 0.f;
    for (int k = h * 128; k < h * 128 + 128; ++k)
        v += sAgg[k] * wl2[k * 128 + j] + sOrg[k] * wr2[k * 128 + j];
    sv[t] = v;
    __syncthreads();

    float lv = (t < 128) ? sv[t] + sv[t + 128] + b2v[t] : -1e30f;
    if (t >= 128 && t < 132) {
        int jj = (t - 128) & 1, hh = (t - 128) >> 1;
        float xv = 0.f;
        for (int k = hh * 128; k < hh * 128 + 128; ++k)
            xv += sAgg[k] * wl1[k * 2 + jj] + sOrg[k] * wr1[k * 2 + jj];
        sx[t - 128] = xv;
    }

    if (t < 128) red[t] = lv;
    __syncthreads();
    for (int off = 64; off > 0; off >>= 1) {
        if (t < off) red[t] = fmaxf(red[t], red[t + off]);
        __syncthreads();
    }
    float m = red[0];
    __syncthreads();
    float e = (t < 128) ? expf(lv - m) : 0.f;
    if (t < 128) red[t] = e;
    __syncthreads();
    for (int off = 64; off > 0; off >>= 1) {
        if (t < off) red[t] += red[t + off];
        __syncthreads();
    }
    float denom = red[0];
    __syncthreads();
    float p = e / denom;
    if (t < 128) {
        g_ssoft[i * 128 + t] = p;
        red[t] = -p * logf(p + 1e-15f);
    }
    __syncthreads();
    for (int off = 64; off > 0; off >>= 1) {
        if (t < off) red[t] += red[t + off];
        __syncthreads();
    }
    if (t == 0) atomicAdd(&g_scal[1], red[0]);
    if (t < 2) g_x1[i * 2 + t] = sx[t] + sx[t + 2] + b1v[t];
}

__global__ void __launch_bounds__(128) k_tmp() {
    int i = blockIdx.x, c = threadIdx.x;
    const float* ar = &g_adj[i * NNODE];
    float v = 0.f;
    for (int k = 0; k < NNODE; ++k) v += ar[k] * g_ssoft[k * NCLUS + c];
    g_tmp[i * NCLUS + c] = v;
}

__global__ void __launch_bounds__(256) k_link() {
    int i = blockIdx.x, j = threadIdx.x;
    __shared__ float rowi[128];
    if (j < 128) rowi[j] = g_ssoft[i * NCLUS + j];
    __syncthreads();
    float d = 0.f;
    const float* rj = &g_ssoft[j * NCLUS];
    for (int c = 0; c < NCLUS; ++c) d += rowi[c] * rj[c];
    float diff = g_adj[i * NNODE + j] - d;
    float sq = diff * diff;
    __shared__ float red[256];
    red[j] = sq; __syncthreads();
    for (int off = 128; off > 0; off >>= 1) {
        if (j < off) red[j] += red[j + off];
        __syncthreads();
    }
    if (j == 0) atomicAdd(&g_scal[0], red[0]);
}

__global__ void __launch_bounds__(256) k_xpool(float* __restrict__ dout) {
    int t = threadIdx.x;
    int c = t >> 1, j = t & 1;
    float v = 0.f;
    for (int i = 0; i < NNODE; ++i)
        v += g_ssoft[i * NCLUS + c] * g_x1[i * 2 + j];
    float nd = tanhf(v);
    g_nodes[c * 2 + j] = nd;
    dout[258 + c * 2 + j] = nd;
}

// Fused: adjpool row r (ssoft^T @ tmp) -> rowmax -> edge_bin
__global__ void __launch_bounds__(128) k_adjebin(float* __restrict__ dout) {
    int r = blockIdx.x, c = threadIdx.x;
    float v = 0.f;
    for (int i = 0; i < NNODE; ++i)
        v += g_ssoft[i * NCLUS + r] * g_tmp[i * NCLUS + c];
    __shared__ float red[128];
    red[c] = v; __syncthreads();
    for (int off = 64; off > 0; off >>= 1) {
        if (c < off) red[c] = fmaxf(red[c], red[c + off]);
        __syncthreads();
    }
    float eb = (v == red[0]) ? 1.f : 0.f;
    g_ebin[r * NCLUS + c] = eb;
    dout[514 + r * NCLUS + c] = eb;
}

__global__ void __launch_bounds__(128) k_final(const float* __restrict__ wl,
                                               const float* __restrict__ wr,
                                               const float* __restrict__ bb,
                                               float* __restrict__ dout) {
    int c = threadIdx.x;
    float ind = 0.f, a0 = 0.f, a1 = 0.f;
    for (int r = 0; r < NCLUS; ++r) {
        float e = g_ebin[r * NCLUS + c];
        ind += e;
        a0 += e * g_nodes[r * 2];
        a1 += e * g_nodes[r * 2 + 1];
    }
    if (ind > 0.f) { a0 /= ind; a1 /= ind; } else { a0 = 0.f; a1 = 0.f; }
    float n0 = g_nodes[c * 2], n1 = g_nodes[c * 2 + 1];
#pragma unroll
    for (int j = 0; j < 2; ++j) {
        float o = a0 * wl[j] + a1 * wl[2 + j] + bb[j] + n0 * wr[j] + n1 * wr[2 + j];
        dout[c * 2 + j] = o;
    }
    if (c == 0) {
        dout[256] = sqrtf(g_scal[0]) / 65536.f;
        dout[257] = g_scal[1] / 256.f;
    }
}

// ---------------------------------------------------------------------------
extern "C" void kernel_launch(void* const* d_in, const int* in_sizes, int n_in,
                              void* d_out, int out_size) {
    const float* x    = (const float*)d_in[0];
    const int*   ei   = (const int*)d_in[1];
    const float* w1   = (const float*)d_in[2];
    const float* b1   = (const float*)d_in[3];
    const float* w2   = (const float*)d_in[4];
    const float* b2   = (const float*)d_in[5];
    const float* w3   = (const float*)d_in[6];
    const float* b3   = (const float*)d_in[7];
    const float* w4   = (const float*)d_in[8];
    const float* b4   = (const float*)d_in[9];
    const float* w5   = (const float*)d_in[10];
    const float* b5   = (const float*)d_in[11];
    const float* s1wl = (const float*)d_in[12];
    const float* s1wr = (const float*)d_in[13];
    const float* s1b  = (const float*)d_in[14];
    const float* s2wl = (const float*)d_in[15];
    const float* s2wr = (const float*)d_in[16];
    const float* s2b  = (const float*)d_in[17];
    const float* s3wl = (const float*)d_in[18];
    const float* s3wr = (const float*)d_in[19];
    const float* s3b  = (const float*)d_in[20];
    float* dout = (float*)d_out;

    __nv_bfloat16 *a1h, *a1m, *a2h, *a2m, *a3h, *a3m, *a4h, *a4m, *wph, *wpm;
    float *org;
    cudaGetSymbolAddress((void**)&a1h, g_a1h);
    cudaGetSymbolAddress((void**)&a1m, g_a1m);
    cudaGetSymbolAddress((void**)&a2h, g_a2h);
    cudaGetSymbolAddress((void**)&a2m, g_a2m);
    cudaGetSymbolAddress((void**)&a3h, g_a3h);
    cudaGetSymbolAddress((void**)&a3m, g_a3m);
    cudaGetSymbolAddress((void**)&a4h, g_a4h);
    cudaGetSymbolAddress((void**)&a4m, g_a4m);
    cudaGetSymbolAddress((void**)&wph, g_wph);
    cudaGetSymbolAddress((void**)&wpm, g_wpm);
    cudaGetSymbolAddress((void**)&org, g_org);

    const int SMEM = 2 * (2 * 128 * 80 + 2 * 64 * 80);   // 61440
    cudaFuncSetAttribute(gemm_conv<32, 5, 0>,
                         cudaFuncAttributeMaxDynamicSharedMemorySize, SMEM);
    cudaFuncSetAttribute(gemm_conv<64, 6, 0>,
                         cudaFuncAttributeMaxDynamicSharedMemorySize, SMEM);
    cudaFuncSetAttribute(gemm_conv<128, 7, 0>,
                         cudaFuncAttributeMaxDynamicSharedMemorySize, SMEM);
    cudaFuncSetAttribute(gemm_conv<256, 8, 1>,
                         cudaFuncAttributeMaxDynamicSharedMemorySize, SMEM);

    // weight pack (all layers, one launch)
    k_packall<<<3816, 256>>>(w2, w3, w4, w5, wph, wpm);

    // L1 direct conv -> a1 (258-grid, C=32)
    conv1_k<<<dim3(16, 16, 2), 256>>>(x, w1, b1, a1h + MARGIN, a1m + MARGIN);

    // L2: 32->64, in 258-grid, M=4*128^2=65536 -> a2 (130-grid, C=64)
    gemm_conv<32, 5, 0><<<dim3(512, 1), 256, SMEM>>>(
        a1h + MARGIN, a1m + MARGIN, wph, wpm, b2,
        a2h + MARGIN, a2m + MARGIN, nullptr, 258, 128, 7, 64);

    // L3: 64->128, in 130-grid, M=16384 -> a3 (66-grid, C=128)
    gemm_conv<64, 6, 0><<<dim3(128, 2), 256, SMEM>>>(
        a2h + MARGIN, a2m + MARGIN, wph + 18432, wpm + 18432, b3,
        a3h + MARGIN, a3m + MARGIN, nullptr, 130, 64, 6, 128);

    // L4: 128->256, in 66-grid, M=4096 -> a4 (34-grid, C=256)
    gemm_conv<128, 7, 0><<<dim3(32, 4), 256, SMEM>>>(
        a3h + MARGIN, a3m + MARGIN, wph + 92160, wpm + 92160, b4,
        a4h + MARGIN, a4m + MARGIN, nullptr, 66, 32, 5, 256);

    // L5: 256->256, in 34-grid, M=1024 -> org (channel-major fp32 16x16)
    gemm_conv<256, 8, 1><<<dim3(8, 4), 256, SMEM>>>(
        a4h + MARGIN, a4m + MARGIN, wph + 387072, wpm + 387072, b5,
        nullptr, nullptr, org, 34, 16, 4, 256);

    // graph stage
    k_zero<<<256, 256>>>();
    k_build_adj<<<16, 256>>>(ei);
    k_rowstage<<<256, 256>>>(org, s1wl, s1wr, s1b, s2wl, s2wr, s2b);
    k_tmp<<<256, 128>>>();
    k_link<<<256, 256>>>();
    k_xpool<<<1, 256>>>(dout);
    k_adjebin<<<128, 128>>>(dout);
    k_final<<<1, 128>>>(s3wl, s3wr, s3b, dout);
}